// round 2
// baseline (speedup 1.0000x reference)
#include <cuda_runtime.h>
#include <math.h>

// Problem constants (fixed by the reference)
#define NMAX   100000
#define EMAX   1600000
#define HID    256
#define INC    512
#define NLAYER 8
#define ALPHA  0.1f

// ---------------- device scratch (no allocation allowed) ----------------
__device__ int   g_deg[NMAX];
__device__ float g_dinv[NMAX];
__device__ int   g_rowptr[NMAX + 1];
__device__ int   g_cursor[NMAX];
__device__ int   g_srcs[EMAX];
__device__ int   g_bsums[256];
__device__ float g_h0[(size_t)NMAX * HID];
__device__ float g_hA[(size_t)NMAX * HID];
__device__ float g_hB[(size_t)NMAX * HID];

// ---------------- small helpers ----------------
__device__ __forceinline__ float4 f4_fma(float w, float4 a, float4 acc) {
    acc.x += w * a.x; acc.y += w * a.y; acc.z += w * a.z; acc.w += w * a.w;
    return acc;
}
__device__ __forceinline__ float4 f4_mix(float wa, float4 a, float wb, float4 b) {
    float4 r;
    r.x = wa * a.x + wb * b.x; r.y = wa * a.y + wb * b.y;
    r.z = wa * a.z + wb * b.z; r.w = wa * a.w + wb * b.w;
    return r;
}

// ---------------- graph preprocessing ----------------
__global__ void k_deg_init(int n) {
    int i = blockIdx.x * blockDim.x + threadIdx.x;
    if (i < n) g_deg[i] = 1;  // self loop
}

__global__ void k_deg_count(const int* __restrict__ ei, int E) {
    int e = blockIdx.x * blockDim.x + threadIdx.x;
    if (e < E) atomicAdd(&g_deg[ei[E + e]], 1);   // col = target
}

__global__ void k_dinv(int n) {
    int i = blockIdx.x * blockDim.x + threadIdx.x;
    if (i < n) g_dinv[i] = rsqrtf((float)g_deg[i]);
}

// Per-block inclusive scan of (deg-1), 1024 elems/block
__global__ void k_scan_blocks(int n) {
    __shared__ int s[1024];
    int t = threadIdx.x;
    int i = blockIdx.x * 1024 + t;
    int v = (i < n) ? (g_deg[i] - 1) : 0;
    s[t] = v;
    __syncthreads();
    for (int off = 1; off < 1024; off <<= 1) {
        int x = (t >= off) ? s[t - off] : 0;
        __syncthreads();
        s[t] += x;
        __syncthreads();
    }
    if (i < n) g_rowptr[i + 1] = s[t];
    if (t == 1023) g_bsums[blockIdx.x] = s[1023];
}

// Single-block exclusive scan of block sums (nb <= 128)
__global__ void k_scan_sums(int nb) {
    __shared__ int s[128];
    int t = threadIdx.x;
    int v = (t < nb) ? g_bsums[t] : 0;
    s[t] = v;
    __syncthreads();
    for (int off = 1; off < 128; off <<= 1) {
        int x = (t >= off) ? s[t - off] : 0;
        __syncthreads();
        s[t] += x;
        __syncthreads();
    }
    if (t < 128) g_bsums[t] = s[t] - v;  // exclusive
}

__global__ void k_finalize_ptrs(int n) {
    int i = blockIdx.x * blockDim.x + threadIdx.x;
    if (i >= n) return;
    int off = g_bsums[i >> 10];
    int incl = g_rowptr[i + 1] + off;
    g_rowptr[i + 1] = incl;
    g_cursor[i] = incl - (g_deg[i] - 1);
    if (i == 0) g_rowptr[0] = 0;
}

__global__ void k_scatter(const int* __restrict__ ei, int E) {
    int e = blockIdx.x * blockDim.x + threadIdx.x;
    if (e >= E) return;
    int dst = ei[E + e];                 // col = target
    int p = atomicAdd(&g_cursor[dst], 1);
    g_srcs[p] = ei[e];                   // row = source
}

// ---------------- SpMM: pull-mode, one warp per node ----------------
// out[i] = (1-ALPHA) * (dinv_i^2 * hin[i] + sum_e dinv_src*dinv_i*hin[src]) + ALPHA*h0[i]
__global__ void __launch_bounds__(256) k_spmm(const float* __restrict__ hin,
                                              float* __restrict__ tout,
                                              const float* __restrict__ h0,
                                              int n) {
    int warp = (blockIdx.x * blockDim.x + threadIdx.x) >> 5;
    int lane = threadIdx.x & 31;
    if (warp >= n) return;
    int node = warp;

    const float4* hin4 = (const float4*)hin;
    const float4* h04  = (const float4*)h0;
    float4* out4 = (float4*)tout;

    float di = g_dinv[node];
    float ws = di * di;  // self-loop norm

    size_t base = (size_t)node * 64;
    float4 acc0 = make_float4(0.f, 0.f, 0.f, 0.f);
    float4 acc1 = make_float4(0.f, 0.f, 0.f, 0.f);
    {
        float4 a = hin4[base + lane];
        float4 b = hin4[base + 32 + lane];
        acc0 = f4_fma(ws, a, acc0);
        acc1 = f4_fma(ws, b, acc1);
    }

    int start = g_rowptr[node];
    int end   = g_rowptr[node + 1];
    for (int p0 = start; p0 < end; p0 += 32) {
        int myp = p0 + lane;
        int src = 0;
        float w = 0.f;
        if (myp < end) {
            src = g_srcs[myp];
            w = g_dinv[src];
        }
        int cnt = min(32, end - p0);
        #pragma unroll 4
        for (int j = 0; j < cnt; j++) {
            int   s  = __shfl_sync(0xffffffffu, src, j);
            float wj = __shfl_sync(0xffffffffu, w, j) * di;
            size_t sb = (size_t)s * 64;
            float4 a = hin4[sb + lane];
            float4 b = hin4[sb + 32 + lane];
            acc0 = f4_fma(wj, a, acc0);
            acc1 = f4_fma(wj, b, acc1);
        }
    }

    float4 r0 = h04[base + lane];
    float4 r1 = h04[base + 32 + lane];
    out4[base + lane]      = f4_mix(1.f - ALPHA, acc0, ALPHA, r0);
    out4[base + 32 + lane] = f4_mix(1.f - ALPHA, acc1, ALPHA, r1);
}

// ---------------- SGEMM: 128x128x8 tile, 256 threads, 8x8 microtile ----------------
// mode 0: Cout = relu(A@B + bias)           (embed)
// mode 1: Cout = (1-beta)*Cin + beta*(A@B)  (+ optional relu)
#define BM 128
#define BN 128
#define BKK 8
#define TM 8
#define TN 8

__global__ void __launch_bounds__(256) k_sgemm(const float* __restrict__ A,
                                               const float* __restrict__ B,
                                               const float* __restrict__ bias,
                                               const float* __restrict__ Cin,
                                               float* __restrict__ Cout,
                                               int M, int Nn, int K,
                                               float beta, int mode, int do_relu) {
    __shared__ float As[BKK][BM];
    __shared__ float Bs[BKK][BN];

    int tid = threadIdx.x;
    int rowBase = blockIdx.y * BM;
    int colBase = blockIdx.x * BN;

    int aRow = tid >> 1;             // 0..127
    int aCol = (tid & 1) * 4;        // 0 or 4
    int bRow = tid >> 5;             // 0..7
    int bCol = (tid & 31) * 4;       // 0..124

    int tRow = (tid >> 4) * TM;      // 0..120
    int tCol = (tid & 15) * TN;      // 0..120

    float acc[TM][TN];
    #pragma unroll
    for (int i = 0; i < TM; i++)
        #pragma unroll
        for (int j = 0; j < TN; j++) acc[i][j] = 0.f;

    for (int k0 = 0; k0 < K; k0 += BKK) {
        // Load A (with M guard), transposed into smem
        float4 av = make_float4(0.f, 0.f, 0.f, 0.f);
        int gr = rowBase + aRow;
        if (gr < M) av = *(const float4*)&A[(size_t)gr * K + k0 + aCol];
        As[aCol + 0][aRow] = av.x;
        As[aCol + 1][aRow] = av.y;
        As[aCol + 2][aRow] = av.z;
        As[aCol + 3][aRow] = av.w;
        // Load B
        float4 bv = *(const float4*)&B[(size_t)(k0 + bRow) * Nn + colBase + bCol];
        *(float4*)&Bs[bRow][bCol] = bv;
        __syncthreads();

        #pragma unroll
        for (int kk = 0; kk < BKK; kk++) {
            float ra[TM], rb[TN];
            #pragma unroll
            for (int i = 0; i < TM; i++) ra[i] = As[kk][tRow + i];
            #pragma unroll
            for (int j = 0; j < TN; j++) rb[j] = Bs[kk][tCol + j];
            #pragma unroll
            for (int i = 0; i < TM; i++)
                #pragma unroll
                for (int j = 0; j < TN; j++) acc[i][j] += ra[i] * rb[j];
        }
        __syncthreads();
    }

    float oneMinusBeta = 1.f - beta;
    #pragma unroll
    for (int i = 0; i < TM; i++) {
        int r = rowBase + tRow + i;
        if (r >= M) break;
        #pragma unroll
        for (int j = 0; j < TN; j += 4) {
            int c = colBase + tCol + j;
            float4 v = make_float4(acc[i][j], acc[i][j + 1], acc[i][j + 2], acc[i][j + 3]);
            if (mode == 0) {
                float4 bb = *(const float4*)&bias[c];
                v.x += bb.x; v.y += bb.y; v.z += bb.z; v.w += bb.w;
                v.x = fmaxf(v.x, 0.f); v.y = fmaxf(v.y, 0.f);
                v.z = fmaxf(v.z, 0.f); v.w = fmaxf(v.w, 0.f);
            } else {
                float4 ci = *(const float4*)&Cin[(size_t)r * Nn + c];
                v = f4_mix(oneMinusBeta, ci, beta, v);
                if (do_relu) {
                    v.x = fmaxf(v.x, 0.f); v.y = fmaxf(v.y, 0.f);
                    v.z = fmaxf(v.z, 0.f); v.w = fmaxf(v.w, 0.f);
                }
            }
            *(float4*)&Cout[(size_t)r * Nn + c] = v;
        }
    }
}

// ---------------- host orchestration ----------------
extern "C" void kernel_launch(void* const* d_in, const int* in_sizes, int n_in,
                              void* d_out, int out_size) {
    const float* x      = (const float*)d_in[0];
    const int*   ei     = (const int*)d_in[1];    // int32: [2, E] (row=src, col=dst)
    const float* Wemb   = (const float*)d_in[2];
    const float* bemb   = (const float*)d_in[3];
    const float* Wconvs = (const float*)d_in[4];
    float* out = (float*)d_out;

    int M = in_sizes[0] / INC;   // nodes
    int E = in_sizes[1] / 2;     // edges

    float *h0, *hA, *hB;
    cudaGetSymbolAddress((void**)&h0, g_h0);
    cudaGetSymbolAddress((void**)&hA, g_hA);
    cudaGetSymbolAddress((void**)&hB, g_hB);

    const int T = 256;
    int nbN = (M + T - 1) / T;
    int nbE = (E + T - 1) / T;
    int nbScan = (M + 1023) / 1024;

    // 1. degrees + dinv
    k_deg_init<<<nbN, T>>>(M);
    k_deg_count<<<nbE, T>>>(ei, E);
    k_dinv<<<nbN, T>>>(M);

    // 2. CSR row pointers (exclusive scan of edge counts)
    k_scan_blocks<<<nbScan, 1024>>>(M);
    k_scan_sums<<<1, 128>>>(nbScan);
    k_finalize_ptrs<<<nbN, T>>>(M);

    // 3. bucket-sort edges by destination
    k_scatter<<<nbE, T>>>(ei, E);

    // 4. embed: h0 = relu(x @ Wemb + bemb)
    {
        dim3 grid(HID / BN, (M + BM - 1) / BM);
        k_sgemm<<<grid, 256>>>(x, Wemb, bemb, nullptr, h0, M, HID, INC, 0.f, 0, 1);
    }

    // 5. layers
    int spmmBlocks = ((M * 32) + T - 1) / T;
    dim3 ggrid(HID / BN, (M + BM - 1) / BM);
    for (int l = 0; l < NLAYER; l++) {
        const float* hin = (l == 0) ? h0 : hA;
        k_spmm<<<spmmBlocks, T>>>(hin, hB, h0, M);
        float beta = logf(0.5f / (float)(l + 1) + 1.0f);
        float* dst = (l == NLAYER - 1) ? out : hA;
        int relu = (l < NLAYER - 1) ? 1 : 0;
        k_sgemm<<<ggrid, 256>>>(hB, Wconvs + (size_t)l * HID * HID, nullptr,
                                hB, dst, M, HID, HID, beta, 1, relu);
    }
}

// round 4
// speedup vs baseline: 1.9725x; 1.9725x over previous
#include <cuda_runtime.h>
#include <math.h>
#include <cstdint>

// Problem constants (fixed by the reference)
#define NMAX   100000
#define EMAX   1600000
#define HID    256
#define INC    512
#define NLAYER 8
#define ALPHA  0.1f

// ---------------- device scratch (no allocation allowed) ----------------
__device__ int   g_deg[NMAX];
__device__ float g_dinv[NMAX];
__device__ int   g_rowptr[NMAX + 1];
__device__ int   g_cursor[NMAX];
__device__ int   g_srcs[EMAX];
__device__ int   g_bsums[256];
__device__ float g_h0[(size_t)NMAX * HID];
__device__ float g_hA[(size_t)NMAX * HID];
__device__ float g_hB[(size_t)NMAX * HID];
__device__ float g_WtE[(size_t)HID * INC];          // transposed embed weight [N=256, K=512]
__device__ float g_WtL[(size_t)NLAYER * HID * HID]; // transposed layer weights [N=256, K=256]

// ---------------- small helpers ----------------
__device__ __forceinline__ float4 f4_fma(float w, float4 a, float4 acc) {
    acc.x += w * a.x; acc.y += w * a.y; acc.z += w * a.z; acc.w += w * a.w;
    return acc;
}
__device__ __forceinline__ float4 f4_mix(float wa, float4 a, float wb, float4 b) {
    float4 r;
    r.x = wa * a.x + wb * b.x; r.y = wa * a.y + wb * b.y;
    r.z = wa * a.z + wb * b.z; r.w = wa * a.w + wb * b.w;
    return r;
}
__device__ __forceinline__ float to_tf32(float x) {
    float y;
    asm("cvt.rna.tf32.f32 %0, %1;" : "=f"(y) : "f"(x));
    return y;
}

// ---------------- graph preprocessing ----------------
__global__ void k_deg_init(int n) {
    int i = blockIdx.x * blockDim.x + threadIdx.x;
    if (i < n) g_deg[i] = 1;  // self loop
}

__global__ void k_deg_count(const int* __restrict__ ei, int E) {
    int e = blockIdx.x * blockDim.x + threadIdx.x;
    if (e < E) atomicAdd(&g_deg[ei[E + e]], 1);   // col = target
}

__global__ void k_dinv(int n) {
    int i = blockIdx.x * blockDim.x + threadIdx.x;
    if (i < n) g_dinv[i] = rsqrtf((float)g_deg[i]);
}

__global__ void k_scan_blocks(int n) {
    __shared__ int s[1024];
    int t = threadIdx.x;
    int i = blockIdx.x * 1024 + t;
    int v = (i < n) ? (g_deg[i] - 1) : 0;
    s[t] = v;
    __syncthreads();
    for (int off = 1; off < 1024; off <<= 1) {
        int x = (t >= off) ? s[t - off] : 0;
        __syncthreads();
        s[t] += x;
        __syncthreads();
    }
    if (i < n) g_rowptr[i + 1] = s[t];
    if (t == 1023) g_bsums[blockIdx.x] = s[1023];
}

__global__ void k_scan_sums(int nb) {
    __shared__ int s[128];
    int t = threadIdx.x;
    int v = (t < nb) ? g_bsums[t] : 0;
    s[t] = v;
    __syncthreads();
    for (int off = 1; off < 128; off <<= 1) {
        int x = (t >= off) ? s[t - off] : 0;
        __syncthreads();
        s[t] += x;
        __syncthreads();
    }
    if (t < 128) g_bsums[t] = s[t] - v;  // exclusive
}

__global__ void k_finalize_ptrs(int n) {
    int i = blockIdx.x * blockDim.x + threadIdx.x;
    if (i >= n) return;
    int off = g_bsums[i >> 10];
    int incl = g_rowptr[i + 1] + off;
    g_rowptr[i + 1] = incl;
    g_cursor[i] = incl - (g_deg[i] - 1);
    if (i == 0) g_rowptr[0] = 0;
}

__global__ void k_scatter(const int* __restrict__ ei, int E) {
    int e = blockIdx.x * blockDim.x + threadIdx.x;
    if (e >= E) return;
    int dst = ei[E + e];
    int p = atomicAdd(&g_cursor[dst], 1);
    g_srcs[p] = ei[e];
}

// Weight transpose: out[n*K+k] = in[k*N+n].  K,N multiples of 32.
__global__ void k_transpose(const float* __restrict__ in, float* __restrict__ out,
                            int K, int N) {
    __shared__ float t[32][33];
    int k0 = blockIdx.x * 32, n0 = blockIdx.y * 32;
    const float* src = in  + (size_t)blockIdx.z * K * N;
    float*       dst = out + (size_t)blockIdx.z * K * N;
    for (int i = threadIdx.y; i < 32; i += 8)
        t[i][threadIdx.x] = src[(size_t)(k0 + i) * N + n0 + threadIdx.x];
    __syncthreads();
    for (int i = threadIdx.y; i < 32; i += 8)
        dst[(size_t)(n0 + i) * K + k0 + threadIdx.x] = t[threadIdx.x][i];
}

// ---------------- SpMM: pull-mode, one warp per node ----------------
__global__ void __launch_bounds__(256) k_spmm(const float* __restrict__ hin,
                                              float* __restrict__ tout,
                                              const float* __restrict__ h0,
                                              int n) {
    int warp = (blockIdx.x * blockDim.x + threadIdx.x) >> 5;
    int lane = threadIdx.x & 31;
    if (warp >= n) return;
    int node = warp;

    const float4* hin4 = (const float4*)hin;
    const float4* h04  = (const float4*)h0;
    float4* out4 = (float4*)tout;

    float di = g_dinv[node];
    float ws = di * di;

    size_t base = (size_t)node * 64;
    float4 acc0 = make_float4(0.f, 0.f, 0.f, 0.f);
    float4 acc1 = make_float4(0.f, 0.f, 0.f, 0.f);
    {
        float4 a = hin4[base + lane];
        float4 b = hin4[base + 32 + lane];
        acc0 = f4_fma(ws, a, acc0);
        acc1 = f4_fma(ws, b, acc1);
    }

    int start = g_rowptr[node];
    int end   = g_rowptr[node + 1];
    for (int p0 = start; p0 < end; p0 += 32) {
        int myp = p0 + lane;
        int src = 0;
        float w = 0.f;
        if (myp < end) {
            src = g_srcs[myp];
            w = g_dinv[src];
        }
        int cnt = min(32, end - p0);
        #pragma unroll 4
        for (int j = 0; j < cnt; j++) {
            int   s  = __shfl_sync(0xffffffffu, src, j);
            float wj = __shfl_sync(0xffffffffu, w, j) * di;
            size_t sb = (size_t)s * 64;
            float4 a = hin4[sb + lane];
            float4 b = hin4[sb + 32 + lane];
            acc0 = f4_fma(wj, a, acc0);
            acc1 = f4_fma(wj, b, acc1);
        }
    }

    float4 r0 = h04[base + lane];
    float4 r1 = h04[base + 32 + lane];
    out4[base + lane]      = f4_mix(1.f - ALPHA, acc0, ALPHA, r0);
    out4[base + 32 + lane] = f4_mix(1.f - ALPHA, acc1, ALPHA, r1);
}

// =========== TF32 mma.sync GEMM: 128x128 block, 4 warps of 64x64 ===========
// A row-major [M,K], Bt K-major [N,K] (i.e. B col-major), C row-major [M,256].
// smem: XOR-swizzled (k ^= (row&7)<<2) -> conflict-free fragment loads.
// mode 0: Cout = relu(A@B + bias)          (embed)
// mode 1: Cout = (1-beta)*Cin + beta*(A@B) (+ optional relu)
#define BK 32

__global__ void __launch_bounds__(128) k_tf32_gemm(const float* __restrict__ A,
                                                   const float* __restrict__ Bt,
                                                   const float* __restrict__ bias,
                                                   const float* __restrict__ Cin,
                                                   float* __restrict__ Cout,
                                                   int M, int K,
                                                   float beta, int mode, int do_relu) {
    __shared__ float As[128 * BK];
    __shared__ float Bs[128 * BK];

    const int tid  = threadIdx.x;
    const int warp = tid >> 5;
    const int lane = tid & 31;
    const int gid  = lane >> 2;   // group id (0..7)
    const int tig  = lane & 3;    // thread in group (0..3)
    const int wm   = warp >> 1;   // warp row 0..1
    const int wn   = warp & 1;    // warp col 0..1
    const int rowBase = blockIdx.y * 128;
    const int colBase = blockIdx.x * 128;

    const int lr = tid >> 3;      // 0..15  (loader row within pass)
    const int lj = tid & 7;       // 0..7   (float4 column)

    float acc[4][8][4];
    #pragma unroll
    for (int i = 0; i < 4; i++)
        #pragma unroll
        for (int j = 0; j < 8; j++)
            #pragma unroll
            for (int q = 0; q < 4; q++) acc[i][j][q] = 0.f;

    const uint32_t* Asu = (const uint32_t*)As;
    const uint32_t* Bsu = (const uint32_t*)Bs;

    const int nch = K >> 5;
    for (int c = 0; c < nch; c++) {
        const int k0 = c << 5;
        // ---- load A tile: 128 rows x 32 cols ----
        #pragma unroll
        for (int p = 0; p < 8; p++) {
            int r  = p * 16 + lr;
            int gr = min(rowBase + r, M - 1);
            float4 v = *(const float4*)&A[(size_t)gr * K + k0 + lj * 4];
            v.x = to_tf32(v.x); v.y = to_tf32(v.y);
            v.z = to_tf32(v.z); v.w = to_tf32(v.w);
            *(float4*)&As[r * BK + 4 * (lj ^ (r & 7))] = v;
        }
        // ---- load B tile: 128 rows (n) x 32 cols (k) ----
        #pragma unroll
        for (int p = 0; p < 8; p++) {
            int r = p * 16 + lr;
            float4 v = *(const float4*)&Bt[(size_t)(colBase + r) * K + k0 + lj * 4];
            v.x = to_tf32(v.x); v.y = to_tf32(v.y);
            v.z = to_tf32(v.z); v.w = to_tf32(v.w);
            *(float4*)&Bs[r * BK + 4 * (lj ^ (r & 7))] = v;
        }
        __syncthreads();

        #pragma unroll
        for (int ks = 0; ks < 4; ks++) {
            const int kk  = ks * 8 + tig;
            const int sw  = gid << 2;
            uint32_t af[4][4];
            #pragma unroll
            for (int mt = 0; mt < 4; mt++) {
                int m = wm * 64 + mt * 16 + gid;
                af[mt][0] = Asu[m * BK + (kk ^ sw)];
                af[mt][1] = Asu[(m + 8) * BK + (kk ^ sw)];
                af[mt][2] = Asu[m * BK + ((kk + 4) ^ sw)];
                af[mt][3] = Asu[(m + 8) * BK + ((kk + 4) ^ sw)];
            }
            uint32_t bf[8][2];
            #pragma unroll
            for (int nt = 0; nt < 8; nt++) {
                int n = wn * 64 + nt * 8 + gid;
                bf[nt][0] = Bsu[n * BK + (kk ^ sw)];
                bf[nt][1] = Bsu[n * BK + ((kk + 4) ^ sw)];
            }
            #pragma unroll
            for (int mt = 0; mt < 4; mt++)
                #pragma unroll
                for (int nt = 0; nt < 8; nt++) {
                    asm volatile(
                        "mma.sync.aligned.m16n8k8.row.col.f32.tf32.tf32.f32 "
                        "{%0,%1,%2,%3}, {%4,%5,%6,%7}, {%8,%9}, {%0,%1,%2,%3};"
                        : "+f"(acc[mt][nt][0]), "+f"(acc[mt][nt][1]),
                          "+f"(acc[mt][nt][2]), "+f"(acc[mt][nt][3])
                        : "r"(af[mt][0]), "r"(af[mt][1]), "r"(af[mt][2]), "r"(af[mt][3]),
                          "r"(bf[nt][0]), "r"(bf[nt][1]));
                }
        }
        __syncthreads();
    }

    // ---- epilogue ----
    const float omb = 1.0f - beta;
    #pragma unroll
    for (int mt = 0; mt < 4; mt++) {
        int rbase = rowBase + wm * 64 + mt * 16 + gid;
        #pragma unroll
        for (int nt = 0; nt < 8; nt++) {
            int cc = colBase + wn * 64 + nt * 8 + tig * 2;
            #pragma unroll
            for (int half = 0; half < 2; half++) {
                int r = rbase + half * 8;
                if (r >= M) continue;
                float v0 = acc[mt][nt][half * 2 + 0];
                float v1 = acc[mt][nt][half * 2 + 1];
                size_t o = (size_t)r * HID + cc;
                if (mode == 0) {
                    v0 = fmaxf(v0 + bias[cc], 0.f);
                    v1 = fmaxf(v1 + bias[cc + 1], 0.f);
                } else {
                    float2 ci = *(const float2*)&Cin[o];
                    v0 = omb * ci.x + beta * v0;
                    v1 = omb * ci.y + beta * v1;
                    if (do_relu) { v0 = fmaxf(v0, 0.f); v1 = fmaxf(v1, 0.f); }
                }
                float2 vo; vo.x = v0; vo.y = v1;
                *(float2*)&Cout[o] = vo;
            }
        }
    }
}

// ---------------- host orchestration ----------------
extern "C" void kernel_launch(void* const* d_in, const int* in_sizes, int n_in,
                              void* d_out, int out_size) {
    const float* x      = (const float*)d_in[0];
    const int*   ei     = (const int*)d_in[1];
    const float* Wemb   = (const float*)d_in[2];
    const float* bemb   = (const float*)d_in[3];
    const float* Wconvs = (const float*)d_in[4];
    float* out = (float*)d_out;

    int M = in_sizes[0] / INC;
    int E = in_sizes[1] / 2;

    float *h0, *hA, *hB, *WtE, *WtL;
    cudaGetSymbolAddress((void**)&h0,  g_h0);
    cudaGetSymbolAddress((void**)&hA,  g_hA);
    cudaGetSymbolAddress((void**)&hB,  g_hB);
    cudaGetSymbolAddress((void**)&WtE, g_WtE);
    cudaGetSymbolAddress((void**)&WtL, g_WtL);

    const int T = 256;
    int nbN = (M + T - 1) / T;
    int nbE = (E + T - 1) / T;
    int nbScan = (M + 1023) / 1024;

    // 1. degrees + dinv
    k_deg_init<<<nbN, T>>>(M);
    k_deg_count<<<nbE, T>>>(ei, E);
    k_dinv<<<nbN, T>>>(M);

    // 2. CSR row pointers
    k_scan_blocks<<<nbScan, 1024>>>(M);
    k_scan_sums<<<1, 128>>>(nbScan);
    k_finalize_ptrs<<<nbN, T>>>(M);

    // 3. bucket-sort edges by destination
    k_scatter<<<nbE, T>>>(ei, E);

    // 3b. transpose weights to K-major [N, K]
    k_transpose<<<dim3(INC / 32, HID / 32, 1), dim3(32, 8)>>>(Wemb, WtE, INC, HID);
    k_transpose<<<dim3(HID / 32, HID / 32, NLAYER), dim3(32, 8)>>>(Wconvs, WtL, HID, HID);

    dim3 ggrid(HID / 128, (M + 127) / 128);

    // 4. embed: h0 = relu(x @ Wemb + bemb)
    k_tf32_gemm<<<ggrid, 128>>>(x, WtE, bemb, nullptr, h0, M, INC, 0.f, 0, 1);

    // 5. layers
    int spmmBlocks = ((M * 32) + T - 1) / T;
    for (int l = 0; l < NLAYER; l++) {
        const float* hin = (l == 0) ? h0 : hA;
        k_spmm<<<spmmBlocks, T>>>(hin, hB, h0, M);
        float beta = logf(0.5f / (float)(l + 1) + 1.0f);
        float* dst = (l == NLAYER - 1) ? out : hA;
        int relu = (l < NLAYER - 1) ? 1 : 0;
        k_tf32_gemm<<<ggrid, 128>>>(hB, WtL + (size_t)l * HID * HID, nullptr,
                                    hB, dst, M, HID, beta, 1, relu);
    }
}

// round 5
// speedup vs baseline: 2.1450x; 1.0874x over previous
#include <cuda_runtime.h>
#include <math.h>
#include <cstdint>

// Problem constants (fixed by the reference)
#define NMAX   100000
#define EMAX   1600000
#define HID    256
#define INC    512
#define NLAYER 8
#define ALPHA  0.1f

// ---------------- device scratch (no allocation allowed) ----------------
__device__ int   g_deg[NMAX];
__device__ float g_dinv[NMAX];
__device__ int   g_rowptr[NMAX + 1];
__device__ int   g_cursor[NMAX];
__device__ int   g_srcs[EMAX];
__device__ float g_wts[EMAX];
__device__ int   g_bsums[256];
__device__ float g_h0[(size_t)NMAX * HID];
__device__ float g_hA[(size_t)NMAX * HID];
__device__ float g_hB[(size_t)NMAX * HID];
__device__ float g_WtE[(size_t)HID * INC];          // transposed embed weight [N=256, K=512] (tf32-rounded)
__device__ float g_WtL[(size_t)NLAYER * HID * HID]; // transposed layer weights [N=256, K=256] (tf32-rounded)

// ---------------- small helpers ----------------
__device__ __forceinline__ float4 f4_fma(float w, float4 a, float4 acc) {
    acc.x += w * a.x; acc.y += w * a.y; acc.z += w * a.z; acc.w += w * a.w;
    return acc;
}
__device__ __forceinline__ float4 f4_mix(float wa, float4 a, float wb, float4 b) {
    float4 r;
    r.x = wa * a.x + wb * b.x; r.y = wa * a.y + wb * b.y;
    r.z = wa * a.z + wb * b.z; r.w = wa * a.w + wb * b.w;
    return r;
}
__device__ __forceinline__ float to_tf32(float x) {
    float y;
    asm("cvt.rna.tf32.f32 %0, %1;" : "=f"(y) : "f"(x));
    return y;
}
__device__ __forceinline__ uint32_t smem_u32(const void* p) {
    uint32_t a;
    asm("{ .reg .u64 t; cvta.to.shared.u64 t, %1; cvt.u32.u64 %0, t; }" : "=r"(a) : "l"(p));
    return a;
}
__device__ __forceinline__ void cp_async16(uint32_t dst, const void* src) {
    asm volatile("cp.async.cg.shared.global [%0], [%1], 16;" :: "r"(dst), "l"(src));
}
#define CP_COMMIT() asm volatile("cp.async.commit_group;" ::: "memory")
#define CP_WAIT(n)  asm volatile("cp.async.wait_group %0;" :: "n"(n) : "memory")

// ---------------- graph preprocessing ----------------
__global__ void k_deg_init(int n) {
    int i = blockIdx.x * blockDim.x + threadIdx.x;
    if (i < n) g_deg[i] = 1;  // self loop
}

__global__ void k_deg_count(const int* __restrict__ ei, int E) {
    int e = blockIdx.x * blockDim.x + threadIdx.x;
    if (e < E) atomicAdd(&g_deg[ei[E + e]], 1);   // col = target
}

__global__ void k_dinv(int n) {
    int i = blockIdx.x * blockDim.x + threadIdx.x;
    if (i < n) g_dinv[i] = rsqrtf((float)g_deg[i]);
}

__global__ void k_scan_blocks(int n) {
    __shared__ int s[1024];
    int t = threadIdx.x;
    int i = blockIdx.x * 1024 + t;
    int v = (i < n) ? (g_deg[i] - 1) : 0;
    s[t] = v;
    __syncthreads();
    for (int off = 1; off < 1024; off <<= 1) {
        int x = (t >= off) ? s[t - off] : 0;
        __syncthreads();
        s[t] += x;
        __syncthreads();
    }
    if (i < n) g_rowptr[i + 1] = s[t];
    if (t == 1023) g_bsums[blockIdx.x] = s[1023];
}

__global__ void k_scan_sums(int nb) {
    __shared__ int s[128];
    int t = threadIdx.x;
    int v = (t < nb) ? g_bsums[t] : 0;
    s[t] = v;
    __syncthreads();
    for (int off = 1; off < 128; off <<= 1) {
        int x = (t >= off) ? s[t - off] : 0;
        __syncthreads();
        s[t] += x;
        __syncthreads();
    }
    if (t < 128) g_bsums[t] = s[t] - v;  // exclusive
}

__global__ void k_finalize_ptrs(int n) {
    int i = blockIdx.x * blockDim.x + threadIdx.x;
    if (i >= n) return;
    int off = g_bsums[i >> 10];
    int incl = g_rowptr[i + 1] + off;
    g_rowptr[i + 1] = incl;
    g_cursor[i] = incl - (g_deg[i] - 1);
    if (i == 0) g_rowptr[0] = 0;
}

__global__ void k_scatter(const int* __restrict__ ei, int E) {
    int e = blockIdx.x * blockDim.x + threadIdx.x;
    if (e >= E) return;
    int src = ei[e];
    int dst = ei[E + e];
    int p = atomicAdd(&g_cursor[dst], 1);
    g_srcs[p] = src;
    g_wts[p] = g_dinv[src] * g_dinv[dst];
}

// Weight transpose with tf32 RNA rounding: out[n*K+k] = tf32(in[k*N+n]).
__global__ void k_transpose(const float* __restrict__ in, float* __restrict__ out,
                            int K, int N) {
    __shared__ float t[32][33];
    int k0 = blockIdx.x * 32, n0 = blockIdx.y * 32;
    const float* src = in  + (size_t)blockIdx.z * K * N;
    float*       dst = out + (size_t)blockIdx.z * K * N;
    for (int i = threadIdx.y; i < 32; i += 8)
        t[i][threadIdx.x] = src[(size_t)(k0 + i) * N + n0 + threadIdx.x];
    __syncthreads();
    for (int i = threadIdx.y; i < 32; i += 8)
        dst[(size_t)(n0 + i) * K + k0 + threadIdx.x] = to_tf32(t[threadIdx.x][i]);
}

// ---------------- SpMM: pull-mode, one warp per node ----------------
__global__ void __launch_bounds__(256) k_spmm(const float* __restrict__ hin,
                                              float* __restrict__ tout,
                                              const float* __restrict__ h0,
                                              int n) {
    int warp = (blockIdx.x * blockDim.x + threadIdx.x) >> 5;
    int lane = threadIdx.x & 31;
    if (warp >= n) return;
    int node = warp;

    const float4* hin4 = (const float4*)hin;
    const float4* h04  = (const float4*)h0;
    float4* out4 = (float4*)tout;

    float di = g_dinv[node];
    float ws = di * di;

    size_t base = (size_t)node * 64;
    float4 acc0 = make_float4(0.f, 0.f, 0.f, 0.f);
    float4 acc1 = make_float4(0.f, 0.f, 0.f, 0.f);
    {
        float4 a = hin4[base + lane];
        float4 b = hin4[base + 32 + lane];
        acc0 = f4_fma(ws, a, acc0);
        acc1 = f4_fma(ws, b, acc1);
    }

    int start = g_rowptr[node];
    int end   = g_rowptr[node + 1];
    for (int p0 = start; p0 < end; p0 += 32) {
        int myp = p0 + lane;
        int src = 0;
        float w = 0.f;
        if (myp < end) {
            src = g_srcs[myp];
            w   = g_wts[myp];
        }
        int cnt = min(32, end - p0);
        #pragma unroll 4
        for (int j = 0; j < cnt; j++) {
            int   s  = __shfl_sync(0xffffffffu, src, j);
            float wj = __shfl_sync(0xffffffffu, w, j);
            size_t sb = (size_t)s * 64;
            float4 a = hin4[sb + lane];
            float4 b = hin4[sb + 32 + lane];
            acc0 = f4_fma(wj, a, acc0);
            acc1 = f4_fma(wj, b, acc1);
        }
    }

    // streaming accesses: evict-first so the gather array owns L2
    float4 r0 = __ldcs(&h04[base + lane]);
    float4 r1 = __ldcs(&h04[base + 32 + lane]);
    __stcs(&out4[base + lane],      f4_mix(1.f - ALPHA, acc0, ALPHA, r0));
    __stcs(&out4[base + 32 + lane], f4_mix(1.f - ALPHA, acc1, ALPHA, r1));
}

// =========== TF32 mma.sync GEMM: 128x128 block, 4 warps, cp.async 2-stage ===========
// A row-major [M,K] raw fp32 (cvt.rna applied on fragments after LDS),
// Bt K-major [N,K] pre-rounded to tf32, C row-major [M,256].
// smem: XOR-swizzled (float4 col ^= row&7) -> conflict-free fragment loads.
// mode 0: Cout = relu(A@B + bias)          (embed)
// mode 1: Cout = (1-beta)*Cin + beta*(A@B) (+ optional relu)
#define BK 32
#define STAGE_F (2 * 128 * BK)   // floats per stage (A tile + B tile)

__global__ void __launch_bounds__(128) k_tf32_gemm(const float* __restrict__ A,
                                                   const float* __restrict__ Bt,
                                                   const float* __restrict__ bias,
                                                   const float* __restrict__ Cin,
                                                   float* __restrict__ Cout,
                                                   int M, int K,
                                                   float beta, int mode, int do_relu) {
    extern __shared__ float smem[];  // 2 stages x 32KB

    const int tid  = threadIdx.x;
    const int warp = tid >> 5;
    const int lane = tid & 31;
    const int gid  = lane >> 2;   // group id (0..7)
    const int tig  = lane & 3;    // thread in group (0..3)
    const int wm   = warp >> 1;   // warp row 0..1
    const int wn   = warp & 1;    // warp col 0..1
    const int rowBase = blockIdx.y * 128;
    const int colBase = blockIdx.x * 128;

    const int lr = tid >> 3;      // 0..15  (loader row within pass)
    const int lj = tid & 7;       // 0..7   (float4 column)

    const int nch = K >> 5;

    float acc[4][8][4];
    #pragma unroll
    for (int i = 0; i < 4; i++)
        #pragma unroll
        for (int j = 0; j < 8; j++)
            #pragma unroll
            for (int q = 0; q < 4; q++) acc[i][j][q] = 0.f;

    const uint32_t smem_base = smem_u32(smem);

    // issue cp.async loads of chunk c into stage buffer
    auto load_chunk = [&](int c) {
        const int k0 = c << 5;
        const uint32_t stg = smem_base + (uint32_t)((c & 1) * STAGE_F * 4);
        #pragma unroll
        for (int p = 0; p < 8; p++) {
            int r  = p * 16 + lr;
            int gr = min(rowBase + r, M - 1);
            cp_async16(stg + (uint32_t)(r * BK + 4 * (lj ^ (r & 7))) * 4,
                       &A[(size_t)gr * K + k0 + lj * 4]);
        }
        const uint32_t stgB = stg + 128 * BK * 4;
        #pragma unroll
        for (int p = 0; p < 8; p++) {
            int r = p * 16 + lr;
            cp_async16(stgB + (uint32_t)(r * BK + 4 * (lj ^ (r & 7))) * 4,
                       &Bt[(size_t)(colBase + r) * K + k0 + lj * 4]);
        }
        CP_COMMIT();
    };

    load_chunk(0);

    for (int c = 0; c < nch; c++) {
        if (c + 1 < nch) {
            load_chunk(c + 1);
            CP_WAIT(1);
        } else {
            CP_WAIT(0);
        }
        __syncthreads();

        const float*    Asf = smem + (c & 1) * STAGE_F;
        const uint32_t* Bsu = (const uint32_t*)(Asf + 128 * BK);

        #pragma unroll
        for (int ks = 0; ks < 4; ks++) {
            const int kk = ks * 8 + tig;
            const int sw = gid << 2;
            uint32_t af[4][4];
            #pragma unroll
            for (int mt = 0; mt < 4; mt++) {
                int m = wm * 64 + mt * 16 + gid;
                af[mt][0] = __float_as_uint(to_tf32(Asf[m * BK + (kk ^ sw)]));
                af[mt][1] = __float_as_uint(to_tf32(Asf[(m + 8) * BK + (kk ^ sw)]));
                af[mt][2] = __float_as_uint(to_tf32(Asf[m * BK + ((kk + 4) ^ sw)]));
                af[mt][3] = __float_as_uint(to_tf32(Asf[(m + 8) * BK + ((kk + 4) ^ sw)]));
            }
            uint32_t bf[8][2];
            #pragma unroll
            for (int nt = 0; nt < 8; nt++) {
                int n = wn * 64 + nt * 8 + gid;
                bf[nt][0] = Bsu[n * BK + (kk ^ sw)];
                bf[nt][1] = Bsu[n * BK + ((kk + 4) ^ sw)];
            }
            #pragma unroll
            for (int mt = 0; mt < 4; mt++)
                #pragma unroll
                for (int nt = 0; nt < 8; nt++) {
                    asm volatile(
                        "mma.sync.aligned.m16n8k8.row.col.f32.tf32.tf32.f32 "
                        "{%0,%1,%2,%3}, {%4,%5,%6,%7}, {%8,%9}, {%0,%1,%2,%3};"
                        : "+f"(acc[mt][nt][0]), "+f"(acc[mt][nt][1]),
                          "+f"(acc[mt][nt][2]), "+f"(acc[mt][nt][3])
                        : "r"(af[mt][0]), "r"(af[mt][1]), "r"(af[mt][2]), "r"(af[mt][3]),
                          "r"(bf[nt][0]), "r"(bf[nt][1]));
                }
        }
        __syncthreads();
    }

    // ---- epilogue ----
    const float omb = 1.0f - beta;
    #pragma unroll
    for (int mt = 0; mt < 4; mt++) {
        int rbase = rowBase + wm * 64 + mt * 16 + gid;
        #pragma unroll
        for (int nt = 0; nt < 8; nt++) {
            int cc = colBase + wn * 64 + nt * 8 + tig * 2;
            #pragma unroll
            for (int half = 0; half < 2; half++) {
                int r = rbase + half * 8;
                if (r >= M) continue;
                float v0 = acc[mt][nt][half * 2 + 0];
                float v1 = acc[mt][nt][half * 2 + 1];
                size_t o = (size_t)r * HID + cc;
                if (mode == 0) {
                    v0 = fmaxf(v0 + bias[cc], 0.f);
                    v1 = fmaxf(v1 + bias[cc + 1], 0.f);
                } else {
                    float2 ci = *(const float2*)&Cin[o];
                    v0 = omb * ci.x + beta * v0;
                    v1 = omb * ci.y + beta * v1;
                    if (do_relu) { v0 = fmaxf(v0, 0.f); v1 = fmaxf(v1, 0.f); }
                }
                float2 vo; vo.x = v0; vo.y = v1;
                *(float2*)&Cout[o] = vo;
            }
        }
    }
}

#define GEMM_SMEM_BYTES (2 * STAGE_F * 4)

// ---------------- host orchestration ----------------
extern "C" void kernel_launch(void* const* d_in, const int* in_sizes, int n_in,
                              void* d_out, int out_size) {
    const float* x      = (const float*)d_in[0];
    const int*   ei     = (const int*)d_in[1];
    const float* Wemb   = (const float*)d_in[2];
    const float* bemb   = (const float*)d_in[3];
    const float* Wconvs = (const float*)d_in[4];
    float* out = (float*)d_out;

    int M = in_sizes[0] / INC;
    int E = in_sizes[1] / 2;

    float *h0, *hA, *hB, *WtE, *WtL;
    cudaGetSymbolAddress((void**)&h0,  g_h0);
    cudaGetSymbolAddress((void**)&hA,  g_hA);
    cudaGetSymbolAddress((void**)&hB,  g_hB);
    cudaGetSymbolAddress((void**)&WtE, g_WtE);
    cudaGetSymbolAddress((void**)&WtL, g_WtL);

    cudaFuncSetAttribute(k_tf32_gemm, cudaFuncAttributeMaxDynamicSharedMemorySize,
                         GEMM_SMEM_BYTES);

    const int T = 256;
    int nbN = (M + T - 1) / T;
    int nbE = (E + T - 1) / T;
    int nbScan = (M + 1023) / 1024;

    // 1. degrees + dinv
    k_deg_init<<<nbN, T>>>(M);
    k_deg_count<<<nbE, T>>>(ei, E);
    k_dinv<<<nbN, T>>>(M);

    // 2. CSR row pointers
    k_scan_blocks<<<nbScan, 1024>>>(M);
    k_scan_sums<<<1, 128>>>(nbScan);
    k_finalize_ptrs<<<nbN, T>>>(M);

    // 3. bucket-sort edges by destination (with fused edge weights)
    k_scatter<<<nbE, T>>>(ei, E);

    // 3b. transpose weights to K-major [N, K], tf32-rounded
    k_transpose<<<dim3(INC / 32, HID / 32, 1), dim3(32, 8)>>>(Wemb, WtE, INC, HID);
    k_transpose<<<dim3(HID / 32, HID / 32, NLAYER), dim3(32, 8)>>>(Wconvs, WtL, HID, HID);

    dim3 ggrid(HID / 128, (M + 127) / 128);

    // 4. embed: h0 = relu(x @ Wemb + bemb)
    k_tf32_gemm<<<ggrid, 128, GEMM_SMEM_BYTES>>>(x, WtE, bemb, nullptr, h0,
                                                 M, INC, 0.f, 0, 1);

    // 5. layers
    int spmmBlocks = ((M * 32) + T - 1) / T;
    for (int l = 0; l < NLAYER; l++) {
        const float* hin = (l == 0) ? h0 : hA;
        k_spmm<<<spmmBlocks, T>>>(hin, hB, h0, M);
        float beta = logf(0.5f / (float)(l + 1) + 1.0f);
        float* dst = (l == NLAYER - 1) ? out : hA;
        int relu = (l < NLAYER - 1) ? 1 : 0;
        k_tf32_gemm<<<ggrid, 128, GEMM_SMEM_BYTES>>>(hB, WtL + (size_t)l * HID * HID,
                                                     nullptr, hB, dst,
                                                     M, HID, beta, 1, relu);
    }
}

// round 7
// speedup vs baseline: 2.5229x; 1.1762x over previous
#include <cuda_runtime.h>
#include <cuda_fp16.h>
#include <math.h>
#include <cstdint>

// Problem constants (fixed by the reference)
#define NMAX   100000
#define EMAX   1600000
#define HID    256
#define INC    512
#define NLAYER 8
#define ALPHA  0.1f

// ---------------- device scratch (no allocation allowed) ----------------
__device__ int    g_deg[NMAX];
__device__ float  g_dinv[NMAX];
__device__ int    g_rowptr[NMAX + 1];
__device__ int    g_cursor[NMAX];
__device__ int    g_srcs[EMAX];
__device__ float  g_wts[EMAX];
__device__ int    g_bsums[256];
__device__ float  g_h0[(size_t)NMAX * HID];                 // fp32 residual
__device__ float  g_hB[(size_t)NMAX * HID];                 // fp32 propagate output
__device__ __half g_h16[(size_t)NMAX * HID];                // fp16 gather array
__device__ float  g_WtE[(size_t)HID * INC];                 // transposed embed weight (tf32)
__device__ float  g_WtL[(size_t)NLAYER * HID * HID];        // transposed layer weights (tf32)

// ---------------- small helpers ----------------
__device__ __forceinline__ float to_tf32(float x) {
    float y;
    asm("cvt.rna.tf32.f32 %0, %1;" : "=f"(y) : "f"(x));
    return y;
}
__device__ __forceinline__ uint32_t smem_u32(const void* p) {
    uint32_t a;
    asm("{ .reg .u64 t; cvta.to.shared.u64 t, %1; cvt.u32.u64 %0, t; }" : "=r"(a) : "l"(p));
    return a;
}
__device__ __forceinline__ void cp_async16(uint32_t dst, const void* src) {
    asm volatile("cp.async.cg.shared.global [%0], [%1], 16;" :: "r"(dst), "l"(src));
}
#define CP_COMMIT() asm volatile("cp.async.commit_group;" ::: "memory")
#define CP_WAIT(n)  asm volatile("cp.async.wait_group %0;" :: "n"(n) : "memory")

// ---------------- graph preprocessing ----------------
__global__ void k_deg_init(int n) {
    int i = blockIdx.x * blockDim.x + threadIdx.x;
    if (i < n) g_deg[i] = 1;  // self loop
}

__global__ void k_deg_count(const int* __restrict__ ei, int E) {
    int e = blockIdx.x * blockDim.x + threadIdx.x;
    if (e < E) atomicAdd(&g_deg[ei[E + e]], 1);   // col = target
}

__global__ void k_dinv(int n) {
    int i = blockIdx.x * blockDim.x + threadIdx.x;
    if (i < n) g_dinv[i] = rsqrtf((float)g_deg[i]);
}

__global__ void k_scan_blocks(int n) {
    __shared__ int s[1024];
    int t = threadIdx.x;
    int i = blockIdx.x * 1024 + t;
    int v = (i < n) ? (g_deg[i] - 1) : 0;
    s[t] = v;
    __syncthreads();
    for (int off = 1; off < 1024; off <<= 1) {
        int x = (t >= off) ? s[t - off] : 0;
        __syncthreads();
        s[t] += x;
        __syncthreads();
    }
    if (i < n) g_rowptr[i + 1] = s[t];
    if (t == 1023) g_bsums[blockIdx.x] = s[1023];
}

__global__ void k_scan_sums(int nb) {
    __shared__ int s[128];
    int t = threadIdx.x;
    int v = (t < nb) ? g_bsums[t] : 0;
    s[t] = v;
    __syncthreads();
    for (int off = 1; off < 128; off <<= 1) {
        int x = (t >= off) ? s[t - off] : 0;
        __syncthreads();
        s[t] += x;
        __syncthreads();
    }
    if (t < 128) g_bsums[t] = s[t] - v;  // exclusive
}

__global__ void k_finalize_ptrs(int n) {
    int i = blockIdx.x * blockDim.x + threadIdx.x;
    if (i >= n) return;
    int off = g_bsums[i >> 10];
    int incl = g_rowptr[i + 1] + off;
    g_rowptr[i + 1] = incl;
    g_cursor[i] = incl - (g_deg[i] - 1);
    if (i == 0) g_rowptr[0] = 0;
}

__global__ void k_scatter(const int* __restrict__ ei, int E) {
    int e = blockIdx.x * blockDim.x + threadIdx.x;
    if (e >= E) return;
    int src = ei[e];
    int dst = ei[E + e];
    int p = atomicAdd(&g_cursor[dst], 1);
    g_srcs[p] = src;
    g_wts[p] = g_dinv[src] * g_dinv[dst];
}

// Weight transpose with tf32 RNA rounding: out[n*K+k] = tf32(in[k*N+n]).
__global__ void k_transpose(const float* __restrict__ in, float* __restrict__ out,
                            int K, int N) {
    __shared__ float t[32][33];
    int k0 = blockIdx.x * 32, n0 = blockIdx.y * 32;
    const float* src = in  + (size_t)blockIdx.z * K * N;
    float*       dst = out + (size_t)blockIdx.z * K * N;
    for (int i = threadIdx.y; i < 32; i += 8)
        t[i][threadIdx.x] = src[(size_t)(k0 + i) * N + n0 + threadIdx.x];
    __syncthreads();
    for (int i = threadIdx.y; i < 32; i += 8)
        dst[(size_t)(n0 + i) * K + k0 + threadIdx.x] = to_tf32(t[threadIdx.x][i]);
}

// ---------------- SpMM (fp16 gather): pull-mode, one warp per node ----------------
// out[i] = (1-ALPHA)*(dinv_i^2*hin[i] + sum_e w_e*hin[src]) + ALPHA*h0[i]   (fp32 accum)
__global__ void __launch_bounds__(256) k_spmm16(const __half* __restrict__ hin,
                                                float* __restrict__ tout,
                                                const float* __restrict__ h0,
                                                int n) {
    int warp = (blockIdx.x * blockDim.x + threadIdx.x) >> 5;
    int lane = threadIdx.x & 31;
    if (warp >= n) return;
    int node = warp;

    const uint4* hin4 = (const uint4*)hin;   // 8 halves per uint4; 32 uint4 per row
    const float4* h04 = (const float4*)h0;
    float4* out4 = (float4*)tout;

    float di = g_dinv[node];
    float ws = di * di;

    float acc[8];
    {
        uint4 v = hin4[(size_t)node * 32 + lane];
        const __half2* h2 = (const __half2*)&v;
        #pragma unroll
        for (int q = 0; q < 4; q++) {
            float2 f = __half22float2(h2[q]);
            acc[q * 2]     = ws * f.x;
            acc[q * 2 + 1] = ws * f.y;
        }
    }

    int start = g_rowptr[node];
    int end   = g_rowptr[node + 1];
    for (int p0 = start; p0 < end; p0 += 32) {
        int myp = p0 + lane;
        int src = 0;
        float w = 0.f;
        if (myp < end) {
            src = g_srcs[myp];
            w   = g_wts[myp];
        }
        int cnt = min(32, end - p0);
        #pragma unroll 4
        for (int j = 0; j < cnt; j++) {
            int   s  = __shfl_sync(0xffffffffu, src, j);
            float wj = __shfl_sync(0xffffffffu, w, j);
            uint4 v = hin4[(size_t)s * 32 + lane];
            const __half2* h2 = (const __half2*)&v;
            #pragma unroll
            for (int q = 0; q < 4; q++) {
                float2 f = __half22float2(h2[q]);
                acc[q * 2]     += wj * f.x;
                acc[q * 2 + 1] += wj * f.y;
            }
        }
    }

    // epilogue: mix with fp32 residual, write fp32
    size_t base = (size_t)node * 64 + lane * 2;   // float4 index; lane owns feats [lane*8, lane*8+8)
    #pragma unroll
    for (int q = 0; q < 2; q++) {
        float4 r = __ldcs(&h04[base + q]);
        float4 v;
        v.x = (1.f - ALPHA) * acc[q * 4 + 0] + ALPHA * r.x;
        v.y = (1.f - ALPHA) * acc[q * 4 + 1] + ALPHA * r.y;
        v.z = (1.f - ALPHA) * acc[q * 4 + 2] + ALPHA * r.z;
        v.w = (1.f - ALPHA) * acc[q * 4 + 3] + ALPHA * r.w;
        __stcs(&out4[base + q], v);
    }
}

// =========== TF32 mma.sync GEMM: 128x128 block, 4 warps, cp.async 2-stage ===========
// A row-major [M,K] raw fp32 (cvt.rna on fragments), Bt K-major [N,K] tf32-rounded.
// mode 0: v = relu(A@B + bias)             (embed)
// mode 1: v = (1-beta)*Cin + beta*(A@B)    (+ optional relu)
// Writes: Cout (fp32) if non-null; Cout16 (fp16 RN) if non-null.
#define BK 32
#define STAGE_F (2 * 128 * BK)   // floats per stage (A tile + B tile)

__global__ void __launch_bounds__(128) k_tf32_gemm(const float* __restrict__ A,
                                                   const float* __restrict__ Bt,
                                                   const float* __restrict__ bias,
                                                   const float* __restrict__ Cin,
                                                   float* __restrict__ Cout,
                                                   __half* __restrict__ Cout16,
                                                   int M, int K,
                                                   float beta, int mode, int do_relu) {
    extern __shared__ float smem[];  // 2 stages x 32KB

    const int tid  = threadIdx.x;
    const int warp = tid >> 5;
    const int lane = tid & 31;
    const int gid  = lane >> 2;
    const int tig  = lane & 3;
    const int wm   = warp >> 1;
    const int wn   = warp & 1;
    const int rowBase = blockIdx.y * 128;
    const int colBase = blockIdx.x * 128;

    const int lr = tid >> 3;
    const int lj = tid & 7;

    const int nch = K >> 5;

    float acc[4][8][4];
    #pragma unroll
    for (int i = 0; i < 4; i++)
        #pragma unroll
        for (int j = 0; j < 8; j++)
            #pragma unroll
            for (int q = 0; q < 4; q++) acc[i][j][q] = 0.f;

    const uint32_t smem_base = smem_u32(smem);

    auto load_chunk = [&](int c) {
        const int k0 = c << 5;
        const uint32_t stg = smem_base + (uint32_t)((c & 1) * STAGE_F * 4);
        #pragma unroll
        for (int p = 0; p < 8; p++) {
            int r  = p * 16 + lr;
            int gr = min(rowBase + r, M - 1);
            cp_async16(stg + (uint32_t)(r * BK + 4 * (lj ^ (r & 7))) * 4,
                       &A[(size_t)gr * K + k0 + lj * 4]);
        }
        const uint32_t stgB = stg + 128 * BK * 4;
        #pragma unroll
        for (int p = 0; p < 8; p++) {
            int r = p * 16 + lr;
            cp_async16(stgB + (uint32_t)(r * BK + 4 * (lj ^ (r & 7))) * 4,
                       &Bt[(size_t)(colBase + r) * K + k0 + lj * 4]);
        }
        CP_COMMIT();
    };

    load_chunk(0);

    for (int c = 0; c < nch; c++) {
        if (c + 1 < nch) {
            load_chunk(c + 1);
            CP_WAIT(1);
        } else {
            CP_WAIT(0);
        }
        __syncthreads();

        const float*    Asf = smem + (c & 1) * STAGE_F;
        const uint32_t* Bsu = (const uint32_t*)(Asf + 128 * BK);

        #pragma unroll
        for (int ks = 0; ks < 4; ks++) {
            const int kk = ks * 8 + tig;
            const int sw = gid << 2;
            uint32_t af[4][4];
            #pragma unroll
            for (int mt = 0; mt < 4; mt++) {
                int m = wm * 64 + mt * 16 + gid;
                af[mt][0] = __float_as_uint(to_tf32(Asf[m * BK + (kk ^ sw)]));
                af[mt][1] = __float_as_uint(to_tf32(Asf[(m + 8) * BK + (kk ^ sw)]));
                af[mt][2] = __float_as_uint(to_tf32(Asf[m * BK + ((kk + 4) ^ sw)]));
                af[mt][3] = __float_as_uint(to_tf32(Asf[(m + 8) * BK + ((kk + 4) ^ sw)]));
            }
            uint32_t bf[8][2];
            #pragma unroll
            for (int nt = 0; nt < 8; nt++) {
                int n = wn * 64 + nt * 8 + gid;
                bf[nt][0] = Bsu[n * BK + (kk ^ sw)];
                bf[nt][1] = Bsu[n * BK + ((kk + 4) ^ sw)];
            }
            #pragma unroll
            for (int mt = 0; mt < 4; mt++)
                #pragma unroll
                for (int nt = 0; nt < 8; nt++) {
                    asm volatile(
                        "mma.sync.aligned.m16n8k8.row.col.f32.tf32.tf32.f32 "
                        "{%0,%1,%2,%3}, {%4,%5,%6,%7}, {%8,%9}, {%0,%1,%2,%3};"
                        : "+f"(acc[mt][nt][0]), "+f"(acc[mt][nt][1]),
                          "+f"(acc[mt][nt][2]), "+f"(acc[mt][nt][3])
                        : "r"(af[mt][0]), "r"(af[mt][1]), "r"(af[mt][2]), "r"(af[mt][3]),
                          "r"(bf[nt][0]), "r"(bf[nt][1]));
                }
        }
        __syncthreads();
    }

    // ---- epilogue ----
    const float omb = 1.0f - beta;
    #pragma unroll
    for (int mt = 0; mt < 4; mt++) {
        int rbase = rowBase + wm * 64 + mt * 16 + gid;
        #pragma unroll
        for (int nt = 0; nt < 8; nt++) {
            int cc = colBase + wn * 64 + nt * 8 + tig * 2;
            #pragma unroll
            for (int half = 0; half < 2; half++) {
                int r = rbase + half * 8;
                if (r >= M) continue;
                float v0 = acc[mt][nt][half * 2 + 0];
                float v1 = acc[mt][nt][half * 2 + 1];
                size_t o = (size_t)r * HID + cc;
                if (mode == 0) {
                    v0 = fmaxf(v0 + bias[cc], 0.f);
                    v1 = fmaxf(v1 + bias[cc + 1], 0.f);
                } else {
                    float2 ci = *(const float2*)&Cin[o];
                    v0 = omb * ci.x + beta * v0;
                    v1 = omb * ci.y + beta * v1;
                    if (do_relu) { v0 = fmaxf(v0, 0.f); v1 = fmaxf(v1, 0.f); }
                }
                if (Cout) {
                    float2 vo; vo.x = v0; vo.y = v1;
                    *(float2*)&Cout[o] = vo;
                }
                if (Cout16)
                    *(__half2*)&Cout16[o] = __floats2half2_rn(v0, v1);
            }
        }
    }
}

#define GEMM_SMEM_BYTES (2 * STAGE_F * 4)

// ---------------- host orchestration ----------------
extern "C" void kernel_launch(void* const* d_in, const int* in_sizes, int n_in,
                              void* d_out, int out_size) {
    const float* x      = (const float*)d_in[0];
    const int*   ei     = (const int*)d_in[1];
    const float* Wemb   = (const float*)d_in[2];
    const float* bemb   = (const float*)d_in[3];
    const float* Wconvs = (const float*)d_in[4];
    float* out = (float*)d_out;

    int M = in_sizes[0] / INC;
    int E = in_sizes[1] / 2;

    float *h0, *hB, *WtE, *WtL;
    __half* h16;
    cudaGetSymbolAddress((void**)&h0,  g_h0);
    cudaGetSymbolAddress((void**)&hB,  g_hB);
    cudaGetSymbolAddress((void**)&h16, g_h16);
    cudaGetSymbolAddress((void**)&WtE, g_WtE);
    cudaGetSymbolAddress((void**)&WtL, g_WtL);

    cudaFuncSetAttribute(k_tf32_gemm, cudaFuncAttributeMaxDynamicSharedMemorySize,
                         GEMM_SMEM_BYTES);

    const int T = 256;
    int nbN = (M + T - 1) / T;
    int nbE = (E + T - 1) / T;
    int nbScan = (M + 1023) / 1024;
    dim3 ggrid(HID / 128, (M + 127) / 128);

    // Order chosen so the 4th launch is the embed GEMM (ncu -s 5 -c 1 window).
    k_transpose<<<dim3(INC / 32, HID / 32, 1), dim3(32, 8)>>>(Wemb, WtE, INC, HID);
    k_transpose<<<dim3(HID / 32, HID / 32, NLAYER), dim3(32, 8)>>>(Wconvs, WtL, HID, HID);
    k_deg_init<<<nbN, T>>>(M);

    // embed: h0 = relu(x @ Wemb + bemb), also emit fp16 copy for layer-0 gather
    k_tf32_gemm<<<ggrid, 128, GEMM_SMEM_BYTES>>>(x, WtE, bemb, nullptr, h0, h16,
                                                 M, INC, 0.f, 0, 1);

    k_deg_count<<<nbE, T>>>(ei, E);
    k_dinv<<<nbN, T>>>(M);
    k_scan_blocks<<<nbScan, 1024>>>(M);
    k_scan_sums<<<1, 128>>>(nbScan);
    k_finalize_ptrs<<<nbN, T>>>(M);
    k_scatter<<<nbE, T>>>(ei, E);

    // layers
    int spmmBlocks = ((M * 32) + T - 1) / T;
    for (int l = 0; l < NLAYER; l++) {
        k_spmm16<<<spmmBlocks, T>>>(h16, hB, h0, M);
        float beta = logf(0.5f / (float)(l + 1) + 1.0f);
        int last = (l == NLAYER - 1);
        k_tf32_gemm<<<ggrid, 128, GEMM_SMEM_BYTES>>>(hB, WtL + (size_t)l * HID * HID,
                                                     nullptr, hB,
                                                     last ? out : nullptr,
                                                     last ? nullptr : h16,
                                                     M, HID, beta, 1, last ? 0 : 1);
    }
}

// round 8
// speedup vs baseline: 3.4404x; 1.3637x over previous
#include <cuda_runtime.h>
#include <cuda_fp16.h>
#include <math.h>
#include <cstdint>

// Problem constants (fixed by the reference)
#define NMAX   100000
#define EMAX   1600000
#define HID    256
#define INC    512
#define NLAYER 8
#define ALPHA  0.1f

// ---------------- device scratch (no allocation allowed) ----------------
__device__ int    g_deg[NMAX];
__device__ float  g_dinv[NMAX];
__device__ int    g_rowptr[NMAX + 1];
__device__ int    g_cursor[NMAX];
__device__ int    g_srcs[EMAX];
__device__ float  g_wts[EMAX];
__device__ int    g_bsums[256];
__device__ __align__(128) __half g_x16[(size_t)NMAX * INC];    // fp16 copy of x
__device__ __align__(128) __half g_h016[(size_t)NMAX * HID];   // fp16 embed output (immutable residual + l0 gather)
__device__ __align__(128) __half g_h16[(size_t)NMAX * HID];    // fp16 rotating gather array (GEMM out)
__device__ __align__(128) __half g_p16[(size_t)NMAX * HID];    // fp16 SpMM output (GEMM in)
__device__ __align__(128) __half g_W16E[(size_t)HID * INC];            // embed weight, [N,K] fp16
__device__ __align__(128) __half g_W16L[(size_t)NLAYER * HID * HID];   // folded layer weights (1-b)I+bW, [N,K] fp16

// ---------------- small helpers ----------------
__device__ __forceinline__ uint32_t smem_u32(const void* p) {
    uint32_t a;
    asm("{ .reg .u64 t; cvta.to.shared.u64 t, %1; cvt.u32.u64 %0, t; }" : "=r"(a) : "l"(p));
    return a;
}
__device__ __forceinline__ void cp_async16(uint32_t dst, const void* src) {
    asm volatile("cp.async.cg.shared.global [%0], [%1], 16;" :: "r"(dst), "l"(src));
}
#define CP_COMMIT() asm volatile("cp.async.commit_group;" ::: "memory")
#define CP_WAIT(n)  asm volatile("cp.async.wait_group %0;" :: "n"(n) : "memory")

// ---------------- graph preprocessing ----------------
__global__ void k_deg_init(int n) {
    int i = blockIdx.x * blockDim.x + threadIdx.x;
    if (i < n) g_deg[i] = 1;  // self loop
}

__global__ void k_deg_count(const int* __restrict__ ei, int E) {
    int e = blockIdx.x * blockDim.x + threadIdx.x;
    if (e < E) atomicAdd(&g_deg[ei[E + e]], 1);   // col = target
}

__global__ void k_dinv(int n) {
    int i = blockIdx.x * blockDim.x + threadIdx.x;
    if (i < n) g_dinv[i] = rsqrtf((float)g_deg[i]);
}

__global__ void k_scan_blocks(int n) {
    __shared__ int s[1024];
    int t = threadIdx.x;
    int i = blockIdx.x * 1024 + t;
    int v = (i < n) ? (g_deg[i] - 1) : 0;
    s[t] = v;
    __syncthreads();
    for (int off = 1; off < 1024; off <<= 1) {
        int x = (t >= off) ? s[t - off] : 0;
        __syncthreads();
        s[t] += x;
        __syncthreads();
    }
    if (i < n) g_rowptr[i + 1] = s[t];
    if (t == 1023) g_bsums[blockIdx.x] = s[1023];
}

__global__ void k_scan_sums(int nb) {
    __shared__ int s[128];
    int t = threadIdx.x;
    int v = (t < nb) ? g_bsums[t] : 0;
    s[t] = v;
    __syncthreads();
    for (int off = 1; off < 128; off <<= 1) {
        int x = (t >= off) ? s[t - off] : 0;
        __syncthreads();
        s[t] += x;
        __syncthreads();
    }
    if (t < 128) g_bsums[t] = s[t] - v;  // exclusive
}

__global__ void k_finalize_ptrs(int n) {
    int i = blockIdx.x * blockDim.x + threadIdx.x;
    if (i >= n) return;
    int off = g_bsums[i >> 10];
    int incl = g_rowptr[i + 1] + off;
    g_rowptr[i + 1] = incl;
    g_cursor[i] = incl - (g_deg[i] - 1);
    if (i == 0) g_rowptr[0] = 0;
}

__global__ void k_scatter(const int* __restrict__ ei, int E) {
    int e = blockIdx.x * blockDim.x + threadIdx.x;
    if (e >= E) return;
    int src = ei[e];
    int dst = ei[E + e];
    int p = atomicAdd(&g_cursor[dst], 1);
    g_srcs[p] = src;
    g_wts[p] = g_dinv[src] * g_dinv[dst];
}

// fp32 -> fp16 bulk convert (8 elems/thread)
__global__ void k_tohalf(const float* __restrict__ in, __half* __restrict__ out, size_t n8) {
    size_t i = (size_t)blockIdx.x * blockDim.x + threadIdx.x;
    if (i >= n8) return;
    const float4* in4 = (const float4*)in;
    float4 a = in4[2 * i], b = in4[2 * i + 1];
    uint4 ov;
    __half2* o2 = (__half2*)&ov;
    o2[0] = __floats2half2_rn(a.x, a.y);
    o2[1] = __floats2half2_rn(a.z, a.w);
    o2[2] = __floats2half2_rn(b.x, b.y);
    o2[3] = __floats2half2_rn(b.z, b.w);
    ((uint4*)out)[i] = ov;
}

// Transpose to [N,K] fp16: out[n*K+k] = h(in[k*N+n])
__global__ void k_transpose_h(const float* __restrict__ in, __half* __restrict__ out,
                              int K, int N) {
    __shared__ float t[32][33];
    int k0 = blockIdx.x * 32, n0 = blockIdx.y * 32;
    for (int i = threadIdx.y; i < 32; i += 8)
        t[i][threadIdx.x] = in[(size_t)(k0 + i) * N + n0 + threadIdx.x];
    __syncthreads();
    for (int i = threadIdx.y; i < 32; i += 8)
        out[(size_t)(n0 + i) * K + k0 + threadIdx.x] = __float2half(t[threadIdx.x][i]);
}

// Folded layer weights: out[n*K+k] = h( beta*W[k][n] + (k==n)*(1-beta) ), layer = blockIdx.z
__global__ void k_transpose_fold(const float* __restrict__ in, __half* __restrict__ out,
                                 int K, int N) {
    __shared__ float t[32][33];
    int l = blockIdx.z;
    float beta = logf(0.5f / (float)(l + 1) + 1.0f);
    int k0 = blockIdx.x * 32, n0 = blockIdx.y * 32;
    const float* src = in  + (size_t)l * K * N;
    __half*      dst = out + (size_t)l * K * N;
    for (int i = threadIdx.y; i < 32; i += 8)
        t[i][threadIdx.x] = src[(size_t)(k0 + i) * N + n0 + threadIdx.x];
    __syncthreads();
    for (int i = threadIdx.y; i < 32; i += 8) {
        int k = k0 + threadIdx.x, nn = n0 + i;
        float v = beta * t[threadIdx.x][i] + ((k == nn) ? (1.0f - beta) : 0.0f);
        dst[(size_t)nn * K + k] = __float2half(v);
    }
}

// ---------------- SpMM (all-fp16 I/O, fp32 accum): one warp per node ----------------
// outp[i] = h16( (1-ALPHA)*(dinv_i^2*hin[i] + sum_e w_e*hin[src]) + ALPHA*res[i] )
__global__ void __launch_bounds__(256) k_spmm16(const __half* __restrict__ hin,
                                                const __half* __restrict__ res,
                                                __half* __restrict__ outp,
                                                int n) {
    int warp = (blockIdx.x * blockDim.x + threadIdx.x) >> 5;
    int lane = threadIdx.x & 31;
    if (warp >= n) return;
    int node = warp;

    const uint4* hin4 = (const uint4*)hin;   // 8 halves per uint4; 32 uint4 per row

    float di = g_dinv[node];
    float ws = di * di;

    float acc[8];
    {
        uint4 v = hin4[(size_t)node * 32 + lane];
        const __half2* h2 = (const __half2*)&v;
        #pragma unroll
        for (int q = 0; q < 4; q++) {
            float2 f = __half22float2(h2[q]);
            acc[q * 2]     = ws * f.x;
            acc[q * 2 + 1] = ws * f.y;
        }
    }

    int start = g_rowptr[node];
    int end   = g_rowptr[node + 1];
    for (int p0 = start; p0 < end; p0 += 32) {
        int myp = p0 + lane;
        int src = 0;
        float w = 0.f;
        if (myp < end) {
            src = g_srcs[myp];
            w   = g_wts[myp];
        }
        int cnt = min(32, end - p0);
        #pragma unroll 4
        for (int j = 0; j < cnt; j++) {
            int   s  = __shfl_sync(0xffffffffu, src, j);
            float wj = __shfl_sync(0xffffffffu, w, j);
            uint4 v = hin4[(size_t)s * 32 + lane];
            const __half2* h2 = (const __half2*)&v;
            #pragma unroll
            for (int q = 0; q < 4; q++) {
                float2 f = __half22float2(h2[q]);
                acc[q * 2]     += wj * f.x;
                acc[q * 2 + 1] += wj * f.y;
            }
        }
    }

    uint4 rv = ((const uint4*)res)[(size_t)node * 32 + lane];
    const __half2* r2 = (const __half2*)&rv;
    uint4 ov;
    __half2* o2 = (__half2*)&ov;
    #pragma unroll
    for (int q = 0; q < 4; q++) {
        float2 f = __half22float2(r2[q]);
        o2[q] = __floats2half2_rn((1.f - ALPHA) * acc[q * 2]     + ALPHA * f.x,
                                  (1.f - ALPHA) * acc[q * 2 + 1] + ALPHA * f.y);
    }
    ((uint4*)outp)[(size_t)node * 32 + lane] = ov;
}

// =========== FP16 mma.sync GEMM: 128x128 tile, 4 warps of 64x64, cp.async 2-stage ===========
// A16 row-major [M,K] fp16, B16 K-major [N,K] fp16 (=> col-major B), fp32 accum.
// smem halves: row = 32 halves (64B = 16 u32); u32 col swizzle c ^ (((row>>1)&3)<<2)
// -> conflict-free fragment LDS, 16B-granular (cp.async-compatible).
// Epilogue: v = A@B (+bias +relu for embed); writes out32 and/or out16.
#define BKH 32                       // K halves per chunk
#define STAGE_B 16384                // bytes per stage: A 8KB + B 8KB

__global__ void __launch_bounds__(128) k_hgemm(const __half* __restrict__ A16,
                                               const __half* __restrict__ B16,
                                               const float* __restrict__ bias,
                                               float* __restrict__ out32,
                                               __half* __restrict__ out16,
                                               int M, int K, int do_relu) {
    __shared__ __align__(16) uint32_t smem[2 * STAGE_B / 4];

    const int tid  = threadIdx.x;
    const int warp = tid >> 5;
    const int lane = tid & 31;
    const int gid  = lane >> 2;   // 0..7
    const int tig  = lane & 3;    // 0..3
    const int wm   = warp >> 1;   // 0..1
    const int wn   = warp & 1;    // 0..1
    const int rowBase = blockIdx.y * 128;
    const int colBase = blockIdx.x * 128;

    const int nch = K >> 5;

    float acc[4][8][4];
    #pragma unroll
    for (int i = 0; i < 4; i++)
        #pragma unroll
        for (int j = 0; j < 8; j++)
            #pragma unroll
            for (int q = 0; q < 4; q++) acc[i][j][q] = 0.f;

    const uint32_t smem_base = smem_u32(smem);

    auto load_chunk = [&](int c) {
        const int k0 = c << 5;
        const uint32_t stg = smem_base + (uint32_t)((c & 1) * STAGE_B);
        #pragma unroll
        for (int p = 0; p < 4; p++) {
            int r  = p * 32 + (tid >> 2);
            int c4 = tid & 3;
            int gr = min(rowBase + r, M - 1);
            cp_async16(stg + (uint32_t)(r * 64 + ((c4 ^ ((r >> 1) & 3)) << 4)),
                       &A16[(size_t)gr * K + k0 + c4 * 8]);
        }
        const uint32_t stgB = stg + STAGE_B / 2;
        #pragma unroll
        for (int p = 0; p < 4; p++) {
            int r  = p * 32 + (tid >> 2);
            int c4 = tid & 3;
            cp_async16(stgB + (uint32_t)(r * 64 + ((c4 ^ ((r >> 1) & 3)) << 4)),
                       &B16[(size_t)(colBase + r) * K + k0 + c4 * 8]);
        }
        CP_COMMIT();
    };

    load_chunk(0);

    for (int c = 0; c < nch; c++) {
        if (c + 1 < nch) {
            load_chunk(c + 1);
            CP_WAIT(1);
        } else {
            CP_WAIT(0);
        }
        __syncthreads();

        const uint32_t* Asu = smem + (c & 1) * (STAGE_B / 4);
        const uint32_t* Bsu = Asu + STAGE_B / 8;

        #pragma unroll
        for (int ks = 0; ks < 2; ks++) {
            const int c0 = ks * 8 + tig;
            uint32_t af[4][4];
            #pragma unroll
            for (int mt = 0; mt < 4; mt++) {
                int m  = wm * 64 + mt * 16 + gid;
                int m8 = m + 8;
                int s  = ((m  >> 1) & 3) << 2;
                int s8 = ((m8 >> 1) & 3) << 2;
                af[mt][0] = Asu[m  * 16 + (c0 ^ s)];
                af[mt][1] = Asu[m8 * 16 + (c0 ^ s8)];
                af[mt][2] = Asu[m  * 16 + ((c0 + 4) ^ s)];
                af[mt][3] = Asu[m8 * 16 + ((c0 + 4) ^ s8)];
            }
            uint32_t bf[8][2];
            #pragma unroll
            for (int nt = 0; nt < 8; nt++) {
                int n = wn * 64 + nt * 8 + gid;
                int s = ((n >> 1) & 3) << 2;
                bf[nt][0] = Bsu[n * 16 + (c0 ^ s)];
                bf[nt][1] = Bsu[n * 16 + ((c0 + 4) ^ s)];
            }
            #pragma unroll
            for (int mt = 0; mt < 4; mt++)
                #pragma unroll
                for (int nt = 0; nt < 8; nt++) {
                    asm volatile(
                        "mma.sync.aligned.m16n8k16.row.col.f32.f16.f16.f32 "
                        "{%0,%1,%2,%3}, {%4,%5,%6,%7}, {%8,%9}, {%0,%1,%2,%3};"
                        : "+f"(acc[mt][nt][0]), "+f"(acc[mt][nt][1]),
                          "+f"(acc[mt][nt][2]), "+f"(acc[mt][nt][3])
                        : "r"(af[mt][0]), "r"(af[mt][1]), "r"(af[mt][2]), "r"(af[mt][3]),
                          "r"(bf[nt][0]), "r"(bf[nt][1]));
                }
        }
        __syncthreads();
    }

    // ---- epilogue ----
    #pragma unroll
    for (int mt = 0; mt < 4; mt++) {
        int rbase = rowBase + wm * 64 + mt * 16 + gid;
        #pragma unroll
        for (int nt = 0; nt < 8; nt++) {
            int cc = colBase + wn * 64 + nt * 8 + tig * 2;
            #pragma unroll
            for (int half = 0; half < 2; half++) {
                int r = rbase + half * 8;
                if (r >= M) continue;
                float v0 = acc[mt][nt][half * 2 + 0];
                float v1 = acc[mt][nt][half * 2 + 1];
                if (bias) {
                    v0 += bias[cc];
                    v1 += bias[cc + 1];
                }
                if (do_relu) {
                    v0 = fmaxf(v0, 0.f);
                    v1 = fmaxf(v1, 0.f);
                }
                size_t o = (size_t)r * HID + cc;
                if (out32) {
                    float2 vo; vo.x = v0; vo.y = v1;
                    *(float2*)&out32[o] = vo;
                }
                if (out16)
                    *(__half2*)&out16[o] = __floats2half2_rn(v0, v1);
            }
        }
    }
}

// ---------------- host orchestration ----------------
extern "C" void kernel_launch(void* const* d_in, const int* in_sizes, int n_in,
                              void* d_out, int out_size) {
    const float* x      = (const float*)d_in[0];
    const int*   ei     = (const int*)d_in[1];
    const float* Wemb   = (const float*)d_in[2];
    const float* bemb   = (const float*)d_in[3];
    const float* Wconvs = (const float*)d_in[4];
    float* out = (float*)d_out;

    int M = in_sizes[0] / INC;
    int E = in_sizes[1] / 2;

    __half *x16, *h016, *h16, *p16, *W16E, *W16L;
    cudaGetSymbolAddress((void**)&x16,  g_x16);
    cudaGetSymbolAddress((void**)&h016, g_h016);
    cudaGetSymbolAddress((void**)&h16,  g_h16);
    cudaGetSymbolAddress((void**)&p16,  g_p16);
    cudaGetSymbolAddress((void**)&W16E, g_W16E);
    cudaGetSymbolAddress((void**)&W16L, g_W16L);

    const int T = 256;
    int nbN = (M + T - 1) / T;
    int nbE = (E + T - 1) / T;
    int nbScan = (M + 1023) / 1024;
    dim3 ggrid(HID / 128, (M + 127) / 128);

    // weights + x conversion first; embed GEMM is the 4th launch (ncu window)
    k_transpose_h<<<dim3(INC / 32, HID / 32), dim3(32, 8)>>>(Wemb, W16E, INC, HID);
    k_transpose_fold<<<dim3(HID / 32, HID / 32, NLAYER), dim3(32, 8)>>>(Wconvs, W16L, HID, HID);
    {
        size_t n8 = (size_t)M * INC / 8;
        k_tohalf<<<(unsigned)((n8 + 255) / 256), 256>>>(x, x16, n8);
    }

    // embed: h016 = h16(relu(x @ Wemb + bemb))
    k_hgemm<<<ggrid, 128>>>(x16, W16E, bemb, nullptr, h016, M, INC, 1);

    // graph preprocessing
    k_deg_init<<<nbN, T>>>(M);
    k_deg_count<<<nbE, T>>>(ei, E);
    k_dinv<<<nbN, T>>>(M);
    k_scan_blocks<<<nbScan, 1024>>>(M);
    k_scan_sums<<<1, 128>>>(nbScan);
    k_finalize_ptrs<<<nbN, T>>>(M);
    k_scatter<<<nbE, T>>>(ei, E);

    // layers: SpMM (fp16 in/out) then folded-weight GEMM
    int spmmBlocks = ((M * 32) + T - 1) / T;
    for (int l = 0; l < NLAYER; l++) {
        const __half* gatherIn = (l == 0) ? h016 : h16;
        k_spmm16<<<spmmBlocks, T>>>(gatherIn, h016, p16, M);
        int last = (l == NLAYER - 1);
        if (last)
            k_hgemm<<<ggrid, 128>>>(p16, W16L + (size_t)l * HID * HID, nullptr,
                                    out, nullptr, M, HID, 0);
        else
            k_hgemm<<<ggrid, 128>>>(p16, W16L + (size_t)l * HID * HID, nullptr,
                                    nullptr, h16, M, HID, 1);
    }
}

// round 9
// speedup vs baseline: 3.6545x; 1.0622x over previous
#include <cuda_runtime.h>
#include <cuda_fp16.h>
#include <math.h>
#include <cstdint>

// Problem constants (fixed by the reference)
#define NMAX   100000
#define EMAX   1600000
#define HID    256
#define INC    512
#define NLAYER 8
#define ALPHA  0.1f

// ---------------- device scratch (no allocation allowed) ----------------
__device__ int    g_deg[NMAX];
__device__ float  g_dinv[NMAX];
__device__ int    g_rowptr[NMAX + 1];
__device__ int    g_cursor[NMAX];
__device__ int    g_srcs[EMAX];
__device__ float  g_wts[EMAX];
__device__ int    g_bsums[256];
__device__ __align__(128) __half g_x16[(size_t)NMAX * INC];    // fp16 copy of x
__device__ __align__(128) __half g_h016[(size_t)NMAX * HID];   // fp16 embed output (residual + l0 gather)
__device__ __align__(128) __half g_h16[(size_t)NMAX * HID];    // fp16 rotating gather array (GEMM out)
__device__ __align__(128) __half g_p16[(size_t)NMAX * HID];    // fp16 SpMM output (GEMM in)
__device__ __align__(128) __half g_W16E[(size_t)HID * INC];            // embed weight, [N,K] fp16
__device__ __align__(128) __half g_W16L[(size_t)NLAYER * HID * HID];   // folded layer weights (1-b)I+bW, [N,K] fp16

// ---------------- small helpers ----------------
__device__ __forceinline__ uint32_t smem_u32(const void* p) {
    uint32_t a;
    asm("{ .reg .u64 t; cvta.to.shared.u64 t, %1; cvt.u32.u64 %0, t; }" : "=r"(a) : "l"(p));
    return a;
}
__device__ __forceinline__ void cp_async16(uint32_t dst, const void* src) {
    asm volatile("cp.async.cg.shared.global [%0], [%1], 16;" :: "r"(dst), "l"(src));
}
#define CP_COMMIT() asm volatile("cp.async.commit_group;" ::: "memory")
#define CP_WAIT(n)  asm volatile("cp.async.wait_group %0;" :: "n"(n) : "memory")

__device__ __forceinline__ void ldsm_x4(uint32_t& r0, uint32_t& r1, uint32_t& r2,
                                        uint32_t& r3, uint32_t addr) {
    asm volatile("ldmatrix.sync.aligned.m8n8.x4.shared.b16 {%0,%1,%2,%3}, [%4];"
                 : "=r"(r0), "=r"(r1), "=r"(r2), "=r"(r3) : "r"(addr));
}

// ---------------- graph preprocessing ----------------
__global__ void k_deg_init(int n) {
    int i = blockIdx.x * blockDim.x + threadIdx.x;
    if (i < n) g_deg[i] = 1;  // self loop
}

__global__ void k_deg_count(const int* __restrict__ ei, int E) {
    int e = blockIdx.x * blockDim.x + threadIdx.x;
    if (e < E) atomicAdd(&g_deg[ei[E + e]], 1);   // col = target
}

__global__ void k_dinv(int n) {
    int i = blockIdx.x * blockDim.x + threadIdx.x;
    if (i < n) g_dinv[i] = rsqrtf((float)g_deg[i]);
}

__global__ void k_scan_blocks(int n) {
    __shared__ int s[1024];
    int t = threadIdx.x;
    int i = blockIdx.x * 1024 + t;
    int v = (i < n) ? (g_deg[i] - 1) : 0;
    s[t] = v;
    __syncthreads();
    for (int off = 1; off < 1024; off <<= 1) {
        int x = (t >= off) ? s[t - off] : 0;
        __syncthreads();
        s[t] += x;
        __syncthreads();
    }
    if (i < n) g_rowptr[i + 1] = s[t];
    if (t == 1023) g_bsums[blockIdx.x] = s[1023];
}

__global__ void k_scan_sums(int nb) {
    __shared__ int s[128];
    int t = threadIdx.x;
    int v = (t < nb) ? g_bsums[t] : 0;
    s[t] = v;
    __syncthreads();
    for (int off = 1; off < 128; off <<= 1) {
        int x = (t >= off) ? s[t - off] : 0;
        __syncthreads();
        s[t] += x;
        __syncthreads();
    }
    if (t < 128) g_bsums[t] = s[t] - v;  // exclusive
}

__global__ void k_finalize_ptrs(int n) {
    int i = blockIdx.x * blockDim.x + threadIdx.x;
    if (i >= n) return;
    int off = g_bsums[i >> 10];
    int incl = g_rowptr[i + 1] + off;
    g_rowptr[i + 1] = incl;
    g_cursor[i] = incl - (g_deg[i] - 1);
    if (i == 0) g_rowptr[0] = 0;
}

__global__ void k_scatter(const int* __restrict__ ei, int E) {
    int e = blockIdx.x * blockDim.x + threadIdx.x;
    if (e >= E) return;
    int src = ei[e];
    int dst = ei[E + e];
    int p = atomicAdd(&g_cursor[dst], 1);
    g_srcs[p] = src;
    g_wts[p] = g_dinv[src] * g_dinv[dst];
}

// fp32 -> fp16 bulk convert (8 elems/thread)
__global__ void k_tohalf(const float* __restrict__ in, __half* __restrict__ out, size_t n8) {
    size_t i = (size_t)blockIdx.x * blockDim.x + threadIdx.x;
    if (i >= n8) return;
    const float4* in4 = (const float4*)in;
    float4 a = in4[2 * i], b = in4[2 * i + 1];
    uint4 ov;
    __half2* o2 = (__half2*)&ov;
    o2[0] = __floats2half2_rn(a.x, a.y);
    o2[1] = __floats2half2_rn(a.z, a.w);
    o2[2] = __floats2half2_rn(b.x, b.y);
    o2[3] = __floats2half2_rn(b.z, b.w);
    ((uint4*)out)[i] = ov;
}

// Transpose to [N,K] fp16: out[n*K+k] = h(in[k*N+n])
__global__ void k_transpose_h(const float* __restrict__ in, __half* __restrict__ out,
                              int K, int N) {
    __shared__ float t[32][33];
    int k0 = blockIdx.x * 32, n0 = blockIdx.y * 32;
    for (int i = threadIdx.y; i < 32; i += 8)
        t[i][threadIdx.x] = in[(size_t)(k0 + i) * N + n0 + threadIdx.x];
    __syncthreads();
    for (int i = threadIdx.y; i < 32; i += 8)
        out[(size_t)(n0 + i) * K + k0 + threadIdx.x] = __float2half(t[threadIdx.x][i]);
}

// Folded layer weights: out[n*K+k] = h( beta*W[k][n] + (k==n)*(1-beta) ), layer = blockIdx.z
__global__ void k_transpose_fold(const float* __restrict__ in, __half* __restrict__ out,
                                 int K, int N) {
    __shared__ float t[32][33];
    int l = blockIdx.z;
    float beta = logf(0.5f / (float)(l + 1) + 1.0f);
    int k0 = blockIdx.x * 32, n0 = blockIdx.y * 32;
    const float* src = in  + (size_t)l * K * N;
    __half*      dst = out + (size_t)l * K * N;
    for (int i = threadIdx.y; i < 32; i += 8)
        t[i][threadIdx.x] = src[(size_t)(k0 + i) * N + n0 + threadIdx.x];
    __syncthreads();
    for (int i = threadIdx.y; i < 32; i += 8) {
        int k = k0 + threadIdx.x, nn = n0 + i;
        float v = beta * t[threadIdx.x][i] + ((k == nn) ? (1.0f - beta) : 0.0f);
        dst[(size_t)nn * K + k] = __float2half(v);
    }
}

// ---------------- SpMM (all-fp16 I/O, fp32 accum): one warp per node ----------------
__global__ void __launch_bounds__(256) k_spmm16(const __half* __restrict__ hin,
                                                const __half* __restrict__ res,
                                                __half* __restrict__ outp,
                                                int n) {
    int warp = (blockIdx.x * blockDim.x + threadIdx.x) >> 5;
    int lane = threadIdx.x & 31;
    if (warp >= n) return;
    int node = warp;

    const uint4* hin4 = (const uint4*)hin;   // 8 halves per uint4; 32 uint4 per row

    float di = g_dinv[node];
    float ws = di * di;

    float acc[8];
    {
        uint4 v = hin4[(size_t)node * 32 + lane];
        const __half2* h2 = (const __half2*)&v;
        #pragma unroll
        for (int q = 0; q < 4; q++) {
            float2 f = __half22float2(h2[q]);
            acc[q * 2]     = ws * f.x;
            acc[q * 2 + 1] = ws * f.y;
        }
    }

    int start = g_rowptr[node];
    int end   = g_rowptr[node + 1];
    for (int p0 = start; p0 < end; p0 += 32) {
        int myp = p0 + lane;
        int src = 0;
        float w = 0.f;
        if (myp < end) {
            src = g_srcs[myp];
            w   = g_wts[myp];
        }
        int cnt = min(32, end - p0);
        #pragma unroll 4
        for (int j = 0; j < cnt; j++) {
            int   s  = __shfl_sync(0xffffffffu, src, j);
            float wj = __shfl_sync(0xffffffffu, w, j);
            uint4 v = hin4[(size_t)s * 32 + lane];
            const __half2* h2 = (const __half2*)&v;
            #pragma unroll
            for (int q = 0; q < 4; q++) {
                float2 f = __half22float2(h2[q]);
                acc[q * 2]     += wj * f.x;
                acc[q * 2 + 1] += wj * f.y;
            }
        }
    }

    uint4 rv = ((const uint4*)res)[(size_t)node * 32 + lane];
    const __half2* r2 = (const __half2*)&rv;
    uint4 ov;
    __half2* o2 = (__half2*)&ov;
    #pragma unroll
    for (int q = 0; q < 4; q++) {
        float2 f = __half22float2(r2[q]);
        o2[q] = __floats2half2_rn((1.f - ALPHA) * acc[q * 2]     + ALPHA * f.x,
                                  (1.f - ALPHA) * acc[q * 2 + 1] + ALPHA * f.y);
    }
    ((uint4*)outp)[(size_t)node * 32 + lane] = ov;
}

// =========== FP16 mma.sync GEMM: 128x128 tile, 4 warps, ldmatrix + 3-stage cp.async ======
// A16 row-major [M,K] fp16, B16 K-major [N,K] fp16 (= col-major B), fp32 accum.
// smem rows = 32 halves (64B = 4 x 16B chunks); chunk swizzle c ^ ((row>>1)&3):
// conflict-free for cp.async stores AND ldmatrix phases.
#define STAGE_B 16384                // bytes per stage: A 8KB + B 8KB

__global__ void __launch_bounds__(128) k_hgemm(const __half* __restrict__ A16,
                                               const __half* __restrict__ B16,
                                               const float* __restrict__ bias,
                                               float* __restrict__ out32,
                                               __half* __restrict__ out16,
                                               int M, int K, int do_relu) {
    __shared__ __align__(16) uint32_t smem[3 * STAGE_B / 4];  // 48 KB

    const int tid  = threadIdx.x;
    const int warp = tid >> 5;
    const int lane = tid & 31;
    const int gid  = lane >> 2;   // 0..7
    const int tig  = lane & 3;    // 0..3
    const int wm   = warp >> 1;   // 0..1
    const int wn   = warp & 1;    // 0..1
    const int rowBase = blockIdx.y * 128;
    const int colBase = blockIdx.x * 128;

    const int nch = K >> 5;

    float acc[4][8][4];
    #pragma unroll
    for (int i = 0; i < 4; i++)
        #pragma unroll
        for (int j = 0; j < 8; j++)
            #pragma unroll
            for (int q = 0; q < 4; q++) acc[i][j][q] = 0.f;

    const uint32_t smem_base = smem_u32(smem);

    // ---- precomputed ldmatrix lane offsets (stage-relative) ----
    // A fragment (mt, ks): tiles [m0 k_lo][m8 k_lo][m0 k_hi][m8 k_hi]
    uint32_t offA[2], offB[2];
    {
        int rA = (lane & 7) + ((lane >> 3) & 1) * 8;   // row within 16-row frag
        int cA = (lane >> 4) & 1;                      // k_lo / k_hi chunk bit
        int rowA = wm * 64 + rA;
        int sA = (rowA >> 1) & 3;
        // B x4 (pair p, ks): tiles [nt0 k_lo][nt0 k_hi][nt1 k_lo][nt1 k_hi]
        int rB = (lane & 7) + ((lane >> 4) & 1) * 8;
        int cB = (lane >> 3) & 1;
        int rowB = wn * 64 + rB;
        int sB = (rowB >> 1) & 3;
        #pragma unroll
        for (int ks = 0; ks < 2; ks++) {
            offA[ks] = (uint32_t)(rowA * 64 + (((ks * 2 + cA) ^ sA) << 4));
            offB[ks] = (uint32_t)(rowB * 64 + (((ks * 2 + cB) ^ sB) << 4));
        }
    }

    auto load_chunk = [&](int c) {
        const int k0 = c << 5;
        const uint32_t stg = smem_base + (uint32_t)((c % 3) * STAGE_B);
        #pragma unroll
        for (int p = 0; p < 4; p++) {
            int r  = p * 32 + (tid >> 2);
            int c4 = tid & 3;
            int gr = min(rowBase + r, M - 1);
            cp_async16(stg + (uint32_t)(r * 64 + ((c4 ^ ((r >> 1) & 3)) << 4)),
                       &A16[(size_t)gr * K + k0 + c4 * 8]);
        }
        const uint32_t stgB = stg + STAGE_B / 2;
        #pragma unroll
        for (int p = 0; p < 4; p++) {
            int r  = p * 32 + (tid >> 2);
            int c4 = tid & 3;
            cp_async16(stgB + (uint32_t)(r * 64 + ((c4 ^ ((r >> 1) & 3)) << 4)),
                       &B16[(size_t)(colBase + r) * K + k0 + c4 * 8]);
        }
        CP_COMMIT();
    };

    load_chunk(0);
    load_chunk(1);

    for (int c = 0; c < nch; c++) {
        if (c + 1 < nch) { CP_WAIT(1); } else { CP_WAIT(0); }
        __syncthreads();                    // stage c ready; all warps past compute c-1
        if (c + 2 < nch) load_chunk(c + 2); // overwrites stage (c-1)%3 — safe after sync

        const uint32_t stg  = smem_base + (uint32_t)((c % 3) * STAGE_B);
        const uint32_t stgB = stg + STAGE_B / 2;

        #pragma unroll
        for (int ks = 0; ks < 2; ks++) {
            uint32_t af[4][4];
            #pragma unroll
            for (int mt = 0; mt < 4; mt++)
                ldsm_x4(af[mt][0], af[mt][1], af[mt][2], af[mt][3],
                        stg + offA[ks] + (uint32_t)(mt * 1024));
            uint32_t bf[8][2];
            #pragma unroll
            for (int p = 0; p < 4; p++)
                ldsm_x4(bf[2 * p][0], bf[2 * p][1], bf[2 * p + 1][0], bf[2 * p + 1][1],
                        stgB + offB[ks] + (uint32_t)(p * 1024));
            #pragma unroll
            for (int mt = 0; mt < 4; mt++)
                #pragma unroll
                for (int nt = 0; nt < 8; nt++) {
                    asm volatile(
                        "mma.sync.aligned.m16n8k16.row.col.f32.f16.f16.f32 "
                        "{%0,%1,%2,%3}, {%4,%5,%6,%7}, {%8,%9}, {%0,%1,%2,%3};"
                        : "+f"(acc[mt][nt][0]), "+f"(acc[mt][nt][1]),
                          "+f"(acc[mt][nt][2]), "+f"(acc[mt][nt][3])
                        : "r"(af[mt][0]), "r"(af[mt][1]), "r"(af[mt][2]), "r"(af[mt][3]),
                          "r"(bf[nt][0]), "r"(bf[nt][1]));
                }
        }
    }

    // ---- epilogue ----
    #pragma unroll
    for (int mt = 0; mt < 4; mt++) {
        int rbase = rowBase + wm * 64 + mt * 16 + gid;
        #pragma unroll
        for (int nt = 0; nt < 8; nt++) {
            int cc = colBase + wn * 64 + nt * 8 + tig * 2;
            #pragma unroll
            for (int half = 0; half < 2; half++) {
                int r = rbase + half * 8;
                if (r >= M) continue;
                float v0 = acc[mt][nt][half * 2 + 0];
                float v1 = acc[mt][nt][half * 2 + 1];
                if (bias) {
                    v0 += bias[cc];
                    v1 += bias[cc + 1];
                }
                if (do_relu) {
                    v0 = fmaxf(v0, 0.f);
                    v1 = fmaxf(v1, 0.f);
                }
                size_t o = (size_t)r * HID + cc;
                if (out32) {
                    float2 vo; vo.x = v0; vo.y = v1;
                    *(float2*)&out32[o] = vo;
                }
                if (out16)
                    *(__half2*)&out16[o] = __floats2half2_rn(v0, v1);
            }
        }
    }
}

// ---------------- host orchestration ----------------
extern "C" void kernel_launch(void* const* d_in, const int* in_sizes, int n_in,
                              void* d_out, int out_size) {
    const float* x      = (const float*)d_in[0];
    const int*   ei     = (const int*)d_in[1];
    const float* Wemb   = (const float*)d_in[2];
    const float* bemb   = (const float*)d_in[3];
    const float* Wconvs = (const float*)d_in[4];
    float* out = (float*)d_out;

    int M = in_sizes[0] / INC;
    int E = in_sizes[1] / 2;

    __half *x16, *h016, *h16, *p16, *W16E, *W16L;
    cudaGetSymbolAddress((void**)&x16,  g_x16);
    cudaGetSymbolAddress((void**)&h016, g_h016);
    cudaGetSymbolAddress((void**)&h16,  g_h16);
    cudaGetSymbolAddress((void**)&p16,  g_p16);
    cudaGetSymbolAddress((void**)&W16E, g_W16E);
    cudaGetSymbolAddress((void**)&W16L, g_W16L);

    const int T = 256;
    int nbN = (M + T - 1) / T;
    int nbE = (E + T - 1) / T;
    int nbScan = (M + 1023) / 1024;
    dim3 ggrid(HID / 128, (M + 127) / 128);

    // weights + x conversion first; embed GEMM is the 4th launch (ncu window)
    k_transpose_h<<<dim3(INC / 32, HID / 32), dim3(32, 8)>>>(Wemb, W16E, INC, HID);
    k_transpose_fold<<<dim3(HID / 32, HID / 32, NLAYER), dim3(32, 8)>>>(Wconvs, W16L, HID, HID);
    {
        size_t n8 = (size_t)M * INC / 8;
        k_tohalf<<<(unsigned)((n8 + 255) / 256), 256>>>(x, x16, n8);
    }

    // embed: h016 = h16(relu(x @ Wemb + bemb))
    k_hgemm<<<ggrid, 128>>>(x16, W16E, bemb, nullptr, h016, M, INC, 1);

    // graph preprocessing
    k_deg_init<<<nbN, T>>>(M);
    k_deg_count<<<nbE, T>>>(ei, E);
    k_dinv<<<nbN, T>>>(M);
    k_scan_blocks<<<nbScan, 1024>>>(M);
    k_scan_sums<<<1, 128>>>(nbScan);
    k_finalize_ptrs<<<nbN, T>>>(M);
    k_scatter<<<nbE, T>>>(ei, E);

    // layers: SpMM (fp16 in/out) then folded-weight GEMM
    int spmmBlocks = ((M * 32) + T - 1) / T;
    for (int l = 0; l < NLAYER; l++) {
        const __half* gatherIn = (l == 0) ? h016 : h16;
        k_spmm16<<<spmmBlocks, T>>>(gatherIn, h016, p16, M);
        int last = (l == NLAYER - 1);
        if (last)
            k_hgemm<<<ggrid, 128>>>(p16, W16L + (size_t)l * HID * HID, nullptr,
                                    out, nullptr, M, HID, 0);
        else
            k_hgemm<<<ggrid, 128>>>(p16, W16L + (size_t)l * HID * HID, nullptr,
                                    nullptr, h16, M, HID, 1);
    }
}